// round 7
// baseline (speedup 1.0000x reference)
#include <cuda_runtime.h>
#include <cstdint>
#include <math.h>

// Problem constants
#define T_    128
#define B_    64
#define TB_   8192      // T*B
#define N_    24        // joints
#define D_    256
#define H_    8
#define F_    32
#define HF_   256       // H*F
#define ND_   6144      // N*D
#define OUTW_ 6144      // N*H*F
#define M1_   196608    // TB*N rows for KV gemm

// Scratch q,k,v in [tb][h][n][f] layout, fp32.
__device__ float g_q[TB_ * H_ * N_ * F_];
__device__ float g_k[TB_ * H_ * N_ * F_];
__device__ float g_v[TB_ * H_ * N_ * F_];

// ---------------------------------------------------------------------------
// helpers
// ---------------------------------------------------------------------------
__device__ __forceinline__ uint32_t smem_u32(const void* p) {
    uint32_t a;
    asm("{ .reg .u64 t; cvta.to.shared.u64 t, %1; cvt.u32.u64 %0, t; }"
        : "=r"(a) : "l"(p));
    return a;
}
__device__ __forceinline__ void cp_async16(uint32_t dst, const void* src) {
    asm volatile("cp.async.cg.shared.global [%0], [%1], 16;"
                 :: "r"(dst), "l"(src) : "memory");
}
__device__ __forceinline__ void cp_commit() {
    asm volatile("cp.async.commit_group;" ::: "memory");
}
__device__ __forceinline__ void cp_wait2() {
    asm volatile("cp.async.wait_group 2;" ::: "memory");
}
__device__ __forceinline__ void cp_wait1() {
    asm volatile("cp.async.wait_group 1;" ::: "memory");
}
__device__ __forceinline__ void cp_wait0() {
    asm volatile("cp.async.wait_group 0;" ::: "memory");
}
// fp32 (smem) -> tf32 reg with round-to-nearest
__device__ __forceinline__ uint32_t ld_tf32(const float* p) {
    uint32_t u;
    asm("cvt.rna.tf32.f32 %0, %1;" : "=r"(u) : "f"(*p));
    return u;
}
__device__ __forceinline__ void mma_tf32(float c[4], const uint32_t a[4],
                                         const uint32_t b[2]) {
    asm volatile(
        "mma.sync.aligned.m16n8k8.row.col.f32.tf32.tf32.f32 "
        "{%0,%1,%2,%3}, {%4,%5,%6,%7}, {%8,%9}, {%0,%1,%2,%3};"
        : "+f"(c[0]), "+f"(c[1]), "+f"(c[2]), "+f"(c[3])
        : "r"(a[0]), "r"(a[1]), "r"(a[2]), "r"(a[3]), "r"(b[0]), "r"(b[1]));
}

// Smem geometry: rows padded to 36 floats; tile A 128x32, B 256x32.
#define APAD     36
#define AT_BYTES (128 * APAD * 4)       // 18432
#define BT_BYTES (256 * APAD * 4)       // 36864
#define STAGE    (AT_BYTES + BT_BYTES)  // 55296
#define NSTG     4
#define GSMEM_BYTES (NSTG * STAGE + 1024)  // 222208 (<227KB, 1 CTA/SM)

// ---------------------------------------------------------------------------
// GEMM inner chunk: CTA 128x256, 16 warps, warp tile 64x32, mma m16n8k8 tf32.
// mWarp = (w&1)*64, nWarp = (w>>1)*32.  c[4][4][4] = 64 accum regs.
// ---------------------------------------------------------------------------
#define GEMM_COMPUTE_CHUNK(sA, sB)                                          \
    {                                                                       \
        _Pragma("unroll")                                                   \
        for (int ks = 0; ks < 4; ks++) {                                    \
            const int kk = ks * 8;                                          \
            uint32_t af[4][4];                                              \
            _Pragma("unroll")                                               \
            for (int mi = 0; mi < 4; mi++) {                                \
                const int r = mWarp + mi * 16 + gid;                        \
                af[mi][0] = ld_tf32(sA + (r)     * APAD + kk + tig);        \
                af[mi][1] = ld_tf32(sA + (r + 8) * APAD + kk + tig);        \
                af[mi][2] = ld_tf32(sA + (r)     * APAD + kk + tig + 4);    \
                af[mi][3] = ld_tf32(sA + (r + 8) * APAD + kk + tig + 4);    \
            }                                                               \
            uint32_t bf[4][2];                                              \
            _Pragma("unroll")                                               \
            for (int ni = 0; ni < 4; ni++) {                                \
                const int nn = nWarp + ni * 8 + gid;                        \
                bf[ni][0] = ld_tf32(sB + nn * APAD + kk + tig);             \
                bf[ni][1] = ld_tf32(sB + nn * APAD + kk + tig + 4);         \
            }                                                               \
            _Pragma("unroll")                                               \
            for (int mi = 0; mi < 4; mi++)                                  \
                _Pragma("unroll")                                           \
                for (int ni = 0; ni < 4; ni++)                              \
                    mma_tf32(c[mi][ni], af[mi], bf[ni]);                    \
        }                                                                   \
    }

#define PIPE_WAIT(ch)                                                       \
    { if ((ch) <= 5) cp_wait2(); else if ((ch) == 6) cp_wait1(); else cp_wait0(); }

// ---------------------------------------------------------------------------
// Kernel 1: K or V projection. grid (1536, 1, 2): x=M tile, z=K/V.
//   CTA computes 128 rows x all 256 output cols; X read once.
// ---------------------------------------------------------------------------
__global__ void __launch_bounds__(512, 1)
kv_mma_kernel(const float* __restrict__ X,
              const float* __restrict__ Wk, const float* __restrict__ bk,
              const float* __restrict__ Wv, const float* __restrict__ bv)
{
    extern __shared__ char smem[];
    const float* W    = (blockIdx.z == 0) ? Wk : Wv;
    const float* bias = (blockIdx.z == 0) ? bk : bv;
    float* dst        = (blockIdx.z == 0) ? g_k : g_v;

    const int tid  = threadIdx.x;
    const int w    = tid >> 5, lane = tid & 31;
    const int gid  = lane >> 2, tig = lane & 3;
    const int mWarp = (w & 1) * 64;
    const int nWarp = (w >> 1) * 32;
    const int rowBase = blockIdx.x * 128;
    const uint32_t sb = smem_u32(smem);

    float* sbias = (float*)(smem + NSTG * STAGE);
    if (tid < 256) sbias[tid] = bias[tid];

    float c[4][4][4];
#pragma unroll
    for (int mi = 0; mi < 4; mi++)
#pragma unroll
        for (int ni = 0; ni < 4; ni++)
#pragma unroll
            for (int j = 0; j < 4; j++) c[mi][ni][j] = 0.f;

    auto load_stage = [&](int ch) {
        const int s = ch & (NSTG - 1);
        const int k0 = ch * 32;
        const uint32_t aBase = sb + s * STAGE;
        const uint32_t bBase = aBase + AT_BYTES;
#pragma unroll
        for (int j = 0; j < 2; j++) {           // A: 128 x 32 = 1024 x 16B
            const int e = tid + 512 * j;
            const int r = e >> 3, c4 = e & 7;
            cp_async16(aBase + (uint32_t)(r * APAD + c4 * 4) * 4,
                       X + (size_t)(rowBase + r) * D_ + k0 + c4 * 4);
        }
#pragma unroll
        for (int j = 0; j < 4; j++) {           // B: 256 x 32 = 2048 x 16B
            const int e = tid + 512 * j;
            const int o = e >> 3, c4 = e & 7;
            cp_async16(bBase + (uint32_t)(o * APAD + c4 * 4) * 4,
                       W + (size_t)o * D_ + k0 + c4 * 4);
        }
    };

    load_stage(0); cp_commit();
    load_stage(1); cp_commit();
    load_stage(2); cp_commit();

    for (int ch = 0; ch < 8; ch++) {
        PIPE_WAIT(ch);
        __syncthreads();                         // single barrier per chunk
        if (ch + 3 < 8) { load_stage(ch + 3); cp_commit(); }
        const float* sA = (const float*)(smem + (ch & (NSTG - 1)) * STAGE);
        const float* sB = (const float*)(smem + (ch & (NSTG - 1)) * STAGE + AT_BYTES);
        GEMM_COMPUTE_CHUNK(sA, sB);
    }

#pragma unroll
    for (int mi = 0; mi < 4; mi++) {
        const int r0 = rowBase + mWarp + mi * 16 + gid;
#pragma unroll
        for (int rr = 0; rr < 2; rr++) {
            const int m = r0 + rr * 8;
            const int tb = m / N_, n = m - tb * N_;
#pragma unroll
            for (int ni = 0; ni < 4; ni++) {
                const int o = nWarp + ni * 8 + tig * 2;
                const int h = o >> 5, f = o & 31;
                float2 v;
                v.x = c[mi][ni][2 * rr + 0] + sbias[o];
                v.y = c[mi][ni][2 * rr + 1] + sbias[o + 1];
                *(float2*)&dst[(((size_t)tb * H_ + h) * N_ + n) * F_ + f] = v;
            }
        }
    }
}

// ---------------------------------------------------------------------------
// Kernel 2: Q projection. grid (64, 1, 24): x=tb tile, z=joint.
// ---------------------------------------------------------------------------
__global__ void __launch_bounds__(512, 1)
q_mma_kernel(const float* __restrict__ X,
             const float* __restrict__ Wq, const float* __restrict__ bq)
{
    extern __shared__ char smem[];
    const int nJ = blockIdx.z;

    const int tid  = threadIdx.x;
    const int w    = tid >> 5, lane = tid & 31;
    const int gid  = lane >> 2, tig = lane & 3;
    const int mWarp = (w & 1) * 64;
    const int nWarp = (w >> 1) * 32;
    const int rowBase = blockIdx.x * 128;
    const uint32_t sb = smem_u32(smem);

    float* sbias = (float*)(smem + NSTG * STAGE);
    if (tid < 256) {
        const int h = tid >> 5, f = tid & 31;
        sbias[tid] = bq[(h * N_ + nJ) * F_ + f];
    }

    float c[4][4][4];
#pragma unroll
    for (int mi = 0; mi < 4; mi++)
#pragma unroll
        for (int ni = 0; ni < 4; ni++)
#pragma unroll
            for (int j = 0; j < 4; j++) c[mi][ni][j] = 0.f;

    auto load_stage = [&](int ch) {
        const int s = ch & (NSTG - 1);
        const int k0 = ch * 32;
        const uint32_t aBase = sb + s * STAGE;
        const uint32_t bBase = aBase + AT_BYTES;
#pragma unroll
        for (int j = 0; j < 2; j++) {           // A: rows tb, stride ND_
            const int e = tid + 512 * j;
            const int r = e >> 3, c4 = e & 7;
            cp_async16(aBase + (uint32_t)(r * APAD + c4 * 4) * 4,
                       X + (size_t)(rowBase + r) * ND_ + nJ * D_ + k0 + c4 * 4);
        }
#pragma unroll
        for (int j = 0; j < 4; j++) {           // B: Wq[h][nJ][f][:]
            const int e = tid + 512 * j;
            const int o = e >> 3, c4 = e & 7;
            const int h = o >> 5, f = o & 31;
            cp_async16(bBase + (uint32_t)(o * APAD + c4 * 4) * 4,
                       Wq + ((size_t)(h * N_ + nJ) * F_ + f) * D_ + k0 + c4 * 4);
        }
    };

    load_stage(0); cp_commit();
    load_stage(1); cp_commit();
    load_stage(2); cp_commit();

    for (int ch = 0; ch < 8; ch++) {
        PIPE_WAIT(ch);
        __syncthreads();
        if (ch + 3 < 8) { load_stage(ch + 3); cp_commit(); }
        const float* sA = (const float*)(smem + (ch & (NSTG - 1)) * STAGE);
        const float* sB = (const float*)(smem + (ch & (NSTG - 1)) * STAGE + AT_BYTES);
        GEMM_COMPUTE_CHUNK(sA, sB);
    }

#pragma unroll
    for (int mi = 0; mi < 4; mi++) {
        const int r0 = rowBase + mWarp + mi * 16 + gid;
#pragma unroll
        for (int rr = 0; rr < 2; rr++) {
            const int tb = r0 + rr * 8;
#pragma unroll
            for (int ni = 0; ni < 4; ni++) {
                const int o = nWarp + ni * 8 + tig * 2;
                const int h = o >> 5, f = o & 31;
                float2 v;
                v.x = c[mi][ni][2 * rr + 0] + sbias[o];
                v.y = c[mi][ni][2 * rr + 1] + sbias[o + 1];
                *(float2*)&g_q[(((size_t)tb * H_ + h) * N_ + nJ) * F_ + f] = v;
            }
        }
    }
}

// ---------------------------------------------------------------------------
// Kernel 3: attention, lane-owns-row. 1 warp per (tb, h), grid (TB, 2) x 128.
// ---------------------------------------------------------------------------
__global__ __launch_bounds__(128)
void attn_kernel(float* __restrict__ out)
{
    __shared__ float  sq[4][N_][33];     // q rows; reused as sout
    __shared__ float4 sk4[4][N_][9];     // k rows as float4 (broadcast reads)
    __shared__ float4 sv4[4][N_][9];     // v rows as float4

    const int tb   = blockIdx.x;
    const int w    = threadIdx.x >> 5;
    const int lane = threadIdx.x & 31;
    const int h    = blockIdx.y * 4 + w;

    const size_t base = ((size_t)(tb * H_ + h)) * N_ * F_;
    const float* qb = g_q + base;
    const float* kb = g_k + base;
    const float* vb = g_v + base;

    for (int i = lane; i < N_ * F_; i += 32)
        sq[w][i >> 5][i & 31] = qb[i];
    for (int i = lane; i < N_ * 8; i += 32) {
        const int r = i >> 3, c = i & 7;
        sk4[w][r][c] = ((const float4*)kb)[i];
        sv4[w][r][c] = ((const float4*)vb)[i];
    }
    __syncwarp();

    const float scale = 0.17677669529663687f;  // 1/sqrt(32)

    float p[N_];
    if (lane < N_) {
        float q[F_];
#pragma unroll
        for (int f = 0; f < F_; f++) q[f] = sq[w][lane][f];

#pragma unroll
        for (int m = 0; m < N_; m++) {
            float acc = 0.f;
#pragma unroll
            for (int c = 0; c < 8; c++) {
                float4 k4 = sk4[w][m][c];
                acc += q[4 * c + 0] * k4.x + q[4 * c + 1] * k4.y
                     + q[4 * c + 2] * k4.z + q[4 * c + 3] * k4.w;
            }
            p[m] = acc * scale;
        }
        float mx = p[0];
#pragma unroll
        for (int m = 1; m < N_; m++) mx = fmaxf(mx, p[m]);
        float sum = 0.f;
#pragma unroll
        for (int m = 0; m < N_; m++) { p[m] = __expf(p[m] - mx); sum += p[m]; }
        const float inv = __frcp_rn(sum);
#pragma unroll
        for (int m = 0; m < N_; m++) p[m] *= inv;
    }
    __syncwarp();   // q reads done; sq becomes sout

    if (lane < N_) {
#pragma unroll
        for (int c = 0; c < 8; c++) {
            float4 acc = make_float4(0.f, 0.f, 0.f, 0.f);
#pragma unroll
            for (int m = 0; m < N_; m++) {
                float4 v4 = sv4[w][m][c];
                acc.x += p[m] * v4.x;  acc.y += p[m] * v4.y;
                acc.z += p[m] * v4.z;  acc.w += p[m] * v4.w;
            }
            sq[w][lane][4 * c + 0] = acc.x;
            sq[w][lane][4 * c + 1] = acc.y;
            sq[w][lane][4 * c + 2] = acc.z;
            sq[w][lane][4 * c + 3] = acc.w;
        }
    }
    __syncwarp();

    for (int i = lane; i < N_ * F_; i += 32) {
        const int n = i >> 5, f = i & 31;
        out[(size_t)tb * OUTW_ + (n * H_ + h) * F_ + f] = sq[w][n][f];
    }
}

// ---------------------------------------------------------------------------
extern "C" void kernel_launch(void* const* d_in, const int* in_sizes, int n_in,
                              void* d_out, int out_size)
{
    const float* x  = (const float*)d_in[0];
    const float* Wk = (const float*)d_in[1];
    const float* bk = (const float*)d_in[2];
    const float* Wv = (const float*)d_in[3];
    const float* bv = (const float*)d_in[4];
    const float* Wq = (const float*)d_in[5];
    const float* bq = (const float*)d_in[6];
    float* out = (float*)d_out;

    cudaFuncSetAttribute(kv_mma_kernel,
                         cudaFuncAttributeMaxDynamicSharedMemorySize, GSMEM_BYTES);
    cudaFuncSetAttribute(q_mma_kernel,
                         cudaFuncAttributeMaxDynamicSharedMemorySize, GSMEM_BYTES);

    dim3 g1(M1_ / 128, 1, 2);
    kv_mma_kernel<<<g1, 512, GSMEM_BYTES>>>(x, Wk, bk, Wv, bv);

    dim3 g2(TB_ / 128, 1, N_);
    q_mma_kernel<<<g2, 512, GSMEM_BYTES>>>(x, Wq, bq);

    dim3 g3(TB_, 2);
    attn_kernel<<<g3, 128>>>(out);
}

// round 9
// speedup vs baseline: 1.2863x; 1.2863x over previous
#include <cuda_runtime.h>
#include <cuda_fp16.h>
#include <cstdint>
#include <math.h>

// Problem constants
#define T_    128
#define B_    64
#define TB_   8192      // T*B
#define N_    24        // joints
#define D_    256
#define H_    8
#define F_    32
#define HF_   256       // H*F
#define ND_   6144      // N*D
#define OUTW_ 6144      // N*H*F
#define M1_   196608    // TB*N rows for KV gemm

// fp16 scratch
__device__ __half g_q[TB_ * H_ * N_ * F_];
__device__ __half g_k[TB_ * H_ * N_ * F_];
__device__ __half g_v[TB_ * H_ * N_ * F_];
// fp16 copies of inputs (pre-converted once)
__device__ __half g_xh[TB_ * ND_];            // X   (100 MB)
__device__ __half g_wkh[HF_ * D_];
__device__ __half g_wvh[HF_ * D_];
__device__ __half g_wqh[H_ * N_ * F_ * D_];

// ---------------------------------------------------------------------------
// helpers
// ---------------------------------------------------------------------------
__device__ __forceinline__ uint32_t smem_u32(const void* p) {
    uint32_t a;
    asm("{ .reg .u64 t; cvta.to.shared.u64 t, %1; cvt.u32.u64 %0, t; }"
        : "=r"(a) : "l"(p));
    return a;
}
__device__ __forceinline__ void cp_async16(uint32_t dst, const void* src) {
    asm volatile("cp.async.cg.shared.global [%0], [%1], 16;"
                 :: "r"(dst), "l"(src) : "memory");
}
__device__ __forceinline__ void cp_commit() {
    asm volatile("cp.async.commit_group;" ::: "memory");
}
__device__ __forceinline__ void cp_wait2() {
    asm volatile("cp.async.wait_group 2;" ::: "memory");
}
__device__ __forceinline__ void cp_wait1() {
    asm volatile("cp.async.wait_group 1;" ::: "memory");
}
__device__ __forceinline__ void cp_wait0() {
    asm volatile("cp.async.wait_group 0;" ::: "memory");
}
// fp16 m16n8k16, fp32 accumulate
__device__ __forceinline__ void mma_f16(float c[4], const uint32_t a[4],
                                        const uint32_t b[2]) {
    asm volatile(
        "mma.sync.aligned.m16n8k16.row.col.f32.f16.f16.f32 "
        "{%0,%1,%2,%3}, {%4,%5,%6,%7}, {%8,%9}, {%0,%1,%2,%3};"
        : "+f"(c[0]), "+f"(c[1]), "+f"(c[2]), "+f"(c[3])
        : "r"(a[0]), "r"(a[1]), "r"(a[2]), "r"(a[3]), "r"(b[0]), "r"(b[1]));
}

// Smem geometry: K-chunk 32 halves = 16 words/row, padded to 20 words (80B).
// Fragment LDS bank check: gid*20 mod 32 = {0,20,8,28,16,4,24,12} -> all
// 8 groups distinct, +tig(0..3) covers all 32 banks. Conflict-free.
#define ROWW     20                         // words per row
#define TILE_BYTES (128 * ROWW * 4)         // 10240
#define STAGE    (2 * TILE_BYTES)           // 20480 (A + B)
#define NSTG     4
#define GSMEM_BYTES (NSTG * STAGE + 1024)   // 82944 -> 2 CTA/SM

// ---------------------------------------------------------------------------
// Pre-pass: fp32 -> fp16, vectorized (float4 -> 4 halves).
// ---------------------------------------------------------------------------
__global__ void conv_h_kernel(const float4* __restrict__ src,
                              uint2* __restrict__ dst, int n4)
{
    for (int i = blockIdx.x * blockDim.x + threadIdx.x; i < n4;
         i += gridDim.x * blockDim.x) {
        float4 v = src[i];
        __half2 a = __floats2half2_rn(v.x, v.y);
        __half2 b = __floats2half2_rn(v.z, v.w);
        uint2 u;
        u.x = *reinterpret_cast<const uint32_t*>(&a);
        u.y = *reinterpret_cast<const uint32_t*>(&b);
        dst[i] = u;
    }
}

// ---------------------------------------------------------------------------
// GEMM inner chunk (K=32): 2 ks-steps of m16n8k16.
// Warp tile 64x32: mWarp=(w&1)*64, nWarp=(w>>1)*32. c[4][4][4].
// Word addressing: row r -> r*ROWW + ks*8 + tig (halves 2tig,2tig+1), +4 = k+8.
// ---------------------------------------------------------------------------
#define GEMM_COMPUTE_CHUNK(sA, sB)                                          \
    {                                                                       \
        _Pragma("unroll")                                                   \
        for (int ks = 0; ks < 2; ks++) {                                    \
            const int kk = ks * 8 + tig;                                    \
            uint32_t af[4][4];                                              \
            _Pragma("unroll")                                               \
            for (int mi = 0; mi < 4; mi++) {                                \
                const int r = mWarp + mi * 16 + gid;                        \
                af[mi][0] = sA[(r)     * ROWW + kk];                        \
                af[mi][1] = sA[(r + 8) * ROWW + kk];                        \
                af[mi][2] = sA[(r)     * ROWW + kk + 4];                    \
                af[mi][3] = sA[(r + 8) * ROWW + kk + 4];                    \
            }                                                               \
            uint32_t bf[4][2];                                              \
            _Pragma("unroll")                                               \
            for (int ni = 0; ni < 4; ni++) {                                \
                const int nn = nWarp + ni * 8 + gid;                        \
                bf[ni][0] = sB[nn * ROWW + kk];                             \
                bf[ni][1] = sB[nn * ROWW + kk + 4];                         \
            }                                                               \
            _Pragma("unroll")                                               \
            for (int mi = 0; mi < 4; mi++)                                  \
                _Pragma("unroll")                                           \
                for (int ni = 0; ni < 4; ni++)                              \
                    mma_f16(c[mi][ni], af[mi], bf[ni]);                     \
        }                                                                   \
    }

#define PIPE_WAIT(ch)                                                       \
    { if ((ch) <= 5) cp_wait2(); else if ((ch) == 6) cp_wait1(); else cp_wait0(); }

// ---------------------------------------------------------------------------
// Kernel 1: K or V projection. grid (2, 2, 1536): x=N-tile, y=K/V, z=M-tile.
//   (x,y fastest -> the 4 CTAs sharing the same X rows run adjacently: L2 reuse)
// ---------------------------------------------------------------------------
__global__ void __launch_bounds__(256, 2)
kv_mma_kernel(const float* __restrict__ bk, const float* __restrict__ bv)
{
    extern __shared__ char smem[];
    const __half* W    = (blockIdx.y == 0) ? g_wkh : g_wvh;
    const float*  bias = (blockIdx.y == 0) ? bk : bv;
    __half*       dst  = (blockIdx.y == 0) ? g_k : g_v;

    const int tid  = threadIdx.x;
    const int w    = tid >> 5, lane = tid & 31;
    const int gid  = lane >> 2, tig = lane & 3;
    const int mWarp = (w & 1) * 64;
    const int nWarp = (w >> 1) * 32;
    const int colBase = blockIdx.x * 128;
    const int rowBase = blockIdx.z * 128;
    const uint32_t sb = smem_u32(smem);

    float* sbias = (float*)(smem + NSTG * STAGE);
    if (tid < 128) sbias[tid] = bias[colBase + tid];

    float c[4][4][4];
#pragma unroll
    for (int mi = 0; mi < 4; mi++)
#pragma unroll
        for (int ni = 0; ni < 4; ni++)
#pragma unroll
            for (int j = 0; j < 4; j++) c[mi][ni][j] = 0.f;

    auto load_stage = [&](int ch) {
        const int s = ch & (NSTG - 1);
        const int k0 = ch * 32;                         // halves
        const uint32_t aBase = sb + s * STAGE;
        const uint32_t bBase = aBase + TILE_BYTES;
#pragma unroll
        for (int j = 0; j < 2; j++) {                   // 512 16B copies each
            const int e = tid + 256 * j;
            const int r = e >> 2, cc = e & 3;           // 4 x 16B per 64B row
            const uint32_t soff = (uint32_t)(r * 80 + cc * 16);
            cp_async16(aBase + soff,
                       g_xh + (size_t)(rowBase + r) * D_ + k0 + cc * 8);
            cp_async16(bBase + soff,
                       W + (size_t)(colBase + r) * D_ + k0 + cc * 8);
        }
    };

    load_stage(0); cp_commit();
    load_stage(1); cp_commit();
    load_stage(2); cp_commit();

    for (int ch = 0; ch < 8; ch++) {
        PIPE_WAIT(ch);
        __syncthreads();
        if (ch + 3 < 8) { load_stage(ch + 3); cp_commit(); }
        const uint32_t* sA = (const uint32_t*)(smem + (ch & (NSTG - 1)) * STAGE);
        const uint32_t* sB = (const uint32_t*)(smem + (ch & (NSTG - 1)) * STAGE + TILE_BYTES);
        GEMM_COMPUTE_CHUNK(sA, sB);
    }

#pragma unroll
    for (int mi = 0; mi < 4; mi++) {
        const int r0 = rowBase + mWarp + mi * 16 + gid;
#pragma unroll
        for (int rr = 0; rr < 2; rr++) {
            const int m = r0 + rr * 8;
            const int tb = m / N_, n = m - tb * N_;
#pragma unroll
            for (int ni = 0; ni < 4; ni++) {
                const int oc = nWarp + ni * 8 + tig * 2;
                const int o = colBase + oc;
                const int h = o >> 5, f = o & 31;
                __half2 v = __floats2half2_rn(c[mi][ni][2 * rr + 0] + sbias[oc],
                                              c[mi][ni][2 * rr + 1] + sbias[oc + 1]);
                *(__half2*)&dst[(((size_t)tb * H_ + h) * N_ + n) * F_ + f] = v;
            }
        }
    }
}

// ---------------------------------------------------------------------------
// Kernel 2: Q projection. grid (2, 24, 64): x=N-tile, y=joint, z=tb-tile.
// ---------------------------------------------------------------------------
__global__ void __launch_bounds__(256, 2)
q_mma_kernel(const float* __restrict__ bq)
{
    extern __shared__ char smem[];
    const int nJ = blockIdx.y;

    const int tid  = threadIdx.x;
    const int w    = tid >> 5, lane = tid & 31;
    const int gid  = lane >> 2, tig = lane & 3;
    const int mWarp = (w & 1) * 64;
    const int nWarp = (w >> 1) * 32;
    const int colBase = blockIdx.x * 128;
    const int rowBase = blockIdx.z * 128;
    const uint32_t sb = smem_u32(smem);

    float* sbias = (float*)(smem + NSTG * STAGE);
    if (tid < 128) {
        const int o = colBase + tid;
        const int h = o >> 5, f = o & 31;
        sbias[tid] = bq[(h * N_ + nJ) * F_ + f];
    }

    float c[4][4][4];
#pragma unroll
    for (int mi = 0; mi < 4; mi++)
#pragma unroll
        for (int ni = 0; ni < 4; ni++)
#pragma unroll
            for (int j = 0; j < 4; j++) c[mi][ni][j] = 0.f;

    auto load_stage = [&](int ch) {
        const int s = ch & (NSTG - 1);
        const int k0 = ch * 32;
        const uint32_t aBase = sb + s * STAGE;
        const uint32_t bBase = aBase + TILE_BYTES;
#pragma unroll
        for (int j = 0; j < 2; j++) {
            const int e = tid + 256 * j;
            const int r = e >> 2, cc = e & 3;
            const uint32_t soff = (uint32_t)(r * 80 + cc * 16);
            cp_async16(aBase + soff,
                       g_xh + (size_t)(rowBase + r) * ND_ + nJ * D_ + k0 + cc * 8);
            const int o = colBase + r;
            const int h = o >> 5, f = o & 31;
            cp_async16(bBase + soff,
                       g_wqh + ((size_t)(h * N_ + nJ) * F_ + f) * D_ + k0 + cc * 8);
        }
    };

    load_stage(0); cp_commit();
    load_stage(1); cp_commit();
    load_stage(2); cp_commit();

    for (int ch = 0; ch < 8; ch++) {
        PIPE_WAIT(ch);
        __syncthreads();
        if (ch + 3 < 8) { load_stage(ch + 3); cp_commit(); }
        const uint32_t* sA = (const uint32_t*)(smem + (ch & (NSTG - 1)) * STAGE);
        const uint32_t* sB = (const uint32_t*)(smem + (ch & (NSTG - 1)) * STAGE + TILE_BYTES);
        GEMM_COMPUTE_CHUNK(sA, sB);
    }

#pragma unroll
    for (int mi = 0; mi < 4; mi++) {
        const int r0 = rowBase + mWarp + mi * 16 + gid;
#pragma unroll
        for (int rr = 0; rr < 2; rr++) {
            const int tb = r0 + rr * 8;
#pragma unroll
            for (int ni = 0; ni < 4; ni++) {
                const int oc = nWarp + ni * 8 + tig * 2;
                const int o = colBase + oc;
                const int h = o >> 5, f = o & 31;
                __half2 v = __floats2half2_rn(c[mi][ni][2 * rr + 0] + sbias[oc],
                                              c[mi][ni][2 * rr + 1] + sbias[oc + 1]);
                *(__half2*)&g_q[(((size_t)tb * H_ + h) * N_ + nJ) * F_ + f] = v;
            }
        }
    }
}

// ---------------------------------------------------------------------------
// Kernel 3: attention, lane-owns-row, fp16 inputs. 1 warp per (tb, h).
// ---------------------------------------------------------------------------
__global__ __launch_bounds__(128)
void attn_kernel(float* __restrict__ out)
{
    __shared__ float  sq[4][N_][33];     // q rows (fp32); reused as sout
    __shared__ float4 sk4[4][N_][9];     // k rows as float4
    __shared__ float4 sv4[4][N_][9];     // v rows as float4

    const int tb   = blockIdx.x;
    const int w    = threadIdx.x >> 5;
    const int lane = threadIdx.x & 31;
    const int h    = blockIdx.y * 4 + w;

    const size_t base = ((size_t)(tb * H_ + h)) * N_ * F_;
    const __half* qb = g_q + base;
    const __half* kb = g_k + base;
    const __half* vb = g_v + base;

    // q: half2 -> two floats
    for (int i = lane; i < N_ * F_ / 2; i += 32) {
        const __half2 hv = ((const __half2*)qb)[i];
        const float2 fv = __half22float2(hv);
        const int r = i >> 4, c2 = (i & 15) * 2;
        sq[w][r][c2] = fv.x; sq[w][r][c2 + 1] = fv.y;
    }
    // k, v: uint2 (4 halves) -> float4
    for (int i = lane; i < N_ * 8; i += 32) {
        const int r = i >> 3, cc = i & 7;
        uint2 ku = ((const uint2*)kb)[i];
        uint2 vu = ((const uint2*)vb)[i];
        float2 k01 = __half22float2(*(__half2*)&ku.x);
        float2 k23 = __half22float2(*(__half2*)&ku.y);
        float2 v01 = __half22float2(*(__half2*)&vu.x);
        float2 v23 = __half22float2(*(__half2*)&vu.y);
        sk4[w][r][cc] = make_float4(k01.x, k01.y, k23.x, k23.y);
        sv4[w][r][cc] = make_float4(v01.x, v01.y, v23.x, v23.y);
    }
    __syncwarp();

    const float scale = 0.17677669529663687f;  // 1/sqrt(32)

    float p[N_];
    if (lane < N_) {
        float q[F_];
#pragma unroll
        for (int f = 0; f < F_; f++) q[f] = sq[w][lane][f];

#pragma unroll
        for (int m = 0; m < N_; m++) {
            float acc = 0.f;
#pragma unroll
            for (int cc = 0; cc < 8; cc++) {
                float4 k4 = sk4[w][m][cc];
                acc += q[4 * cc + 0] * k4.x + q[4 * cc + 1] * k4.y
                     + q[4 * cc + 2] * k4.z + q[4 * cc + 3] * k4.w;
            }
            p[m] = acc * scale;
        }
        float mx = p[0];
#pragma unroll
        for (int m = 1; m < N_; m++) mx = fmaxf(mx, p[m]);
        float sum = 0.f;
#pragma unroll
        for (int m = 0; m < N_; m++) { p[m] = __expf(p[m] - mx); sum += p[m]; }
        const float inv = __frcp_rn(sum);
#pragma unroll
        for (int m = 0; m < N_; m++) p[m] *= inv;
    }
    __syncwarp();   // q reads done; sq becomes sout

    if (lane < N_) {
#pragma unroll
        for (int cc = 0; cc < 8; cc++) {
            float4 acc = make_float4(0.f, 0.f, 0.f, 0.f);
#pragma unroll
            for (int m = 0; m < N_; m++) {
                float4 v4 = sv4[w][m][cc];
                acc.x += p[m] * v4.x;  acc.y += p[m] * v4.y;
                acc.z += p[m] * v4.z;  acc.w += p[m] * v4.w;
            }
            sq[w][lane][4 * cc + 0] = acc.x;
            sq[w][lane][4 * cc + 1] = acc.y;
            sq[w][lane][4 * cc + 2] = acc.z;
            sq[w][lane][4 * cc + 3] = acc.w;
        }
    }
    __syncwarp();

    for (int i = lane; i < N_ * F_; i += 32) {
        const int n = i >> 5, f = i & 31;
        out[(size_t)tb * OUTW_ + (n * H_ + h) * F_ + f] = sq[w][n][f];
    }
}

// ---------------------------------------------------------------------------
extern "C" void kernel_launch(void* const* d_in, const int* in_sizes, int n_in,
                              void* d_out, int out_size)
{
    const float* x  = (const float*)d_in[0];
    const float* Wk = (const float*)d_in[1];
    const float* bk = (const float*)d_in[2];
    const float* Wv = (const float*)d_in[3];
    const float* bv = (const float*)d_in[4];
    const float* Wq = (const float*)d_in[5];
    const float* bq = (const float*)d_in[6];
    float* out = (float*)d_out;

    cudaFuncSetAttribute(kv_mma_kernel,
                         cudaFuncAttributeMaxDynamicSharedMemorySize, GSMEM_BYTES);
    cudaFuncSetAttribute(q_mma_kernel,
                         cudaFuncAttributeMaxDynamicSharedMemorySize, GSMEM_BYTES);

    void* xh; void* wkh; void* wvh; void* wqh;
    cudaGetSymbolAddress(&xh,  g_xh);
    cudaGetSymbolAddress(&wkh, g_wkh);
    cudaGetSymbolAddress(&wvh, g_wvh);
    cudaGetSymbolAddress(&wqh, g_wqh);

    // Pre-pass: fp32 -> fp16 once.
    conv_h_kernel<<<8192, 256>>>((const float4*)x,  (uint2*)xh,  TB_ * ND_ / 4);
    conv_h_kernel<<<64,   256>>>((const float4*)Wk, (uint2*)wkh, HF_ * D_ / 4);
    conv_h_kernel<<<64,   256>>>((const float4*)Wv, (uint2*)wvh, HF_ * D_ / 4);
    conv_h_kernel<<<1536, 256>>>((const float4*)Wq, (uint2*)wqh, H_ * N_ * F_ * D_ / 4);

    dim3 g1(2, 2, M1_ / 128);
    kv_mma_kernel<<<g1, 256, GSMEM_BYTES>>>(bk, bv);

    dim3 g2(2, N_, TB_ / 128);
    q_mma_kernel<<<g2, 256, GSMEM_BYTES>>>(bq);

    dim3 g3(TB_, 2);
    attn_kernel<<<g3, 128>>>(out);
}

// round 10
// speedup vs baseline: 1.3287x; 1.0330x over previous
#include <cuda_runtime.h>
#include <cuda_fp16.h>
#include <cstdint>
#include <math.h>

// Problem constants
#define T_    128
#define B_    64
#define TB_   8192      // T*B
#define N_    24        // joints
#define D_    256
#define H_    8
#define F_    32
#define HF_   256       // H*F
#define ND_   6144      // N*D
#define OUTW_ 6144      // N*H*F
#define M1_   196608    // TB*N rows for KV gemm

// fp16 scratch
__device__ __half g_q[TB_ * H_ * N_ * F_];
__device__ __half g_k[TB_ * H_ * N_ * F_];
__device__ __half g_v[TB_ * H_ * N_ * F_];
// fp16 copies of inputs (pre-converted once)
__device__ __half g_xh[TB_ * ND_];            // X   (100 MB)
__device__ __half g_wkh[HF_ * D_];
__device__ __half g_wvh[HF_ * D_];
__device__ __half g_wqh[H_ * N_ * F_ * D_];

// ---------------------------------------------------------------------------
// helpers
// ---------------------------------------------------------------------------
__device__ __forceinline__ uint32_t smem_u32(const void* p) {
    uint32_t a;
    asm("{ .reg .u64 t; cvta.to.shared.u64 t, %1; cvt.u32.u64 %0, t; }"
        : "=r"(a) : "l"(p));
    return a;
}
__device__ __forceinline__ void cp_async16(uint32_t dst, const void* src) {
    asm volatile("cp.async.cg.shared.global [%0], [%1], 16;"
                 :: "r"(dst), "l"(src) : "memory");
}
__device__ __forceinline__ void cp_commit() {
    asm volatile("cp.async.commit_group;" ::: "memory");
}
__device__ __forceinline__ void cp_wait1() {
    asm volatile("cp.async.wait_group 1;" ::: "memory");
}
__device__ __forceinline__ void cp_wait0() {
    asm volatile("cp.async.wait_group 0;" ::: "memory");
}
// fp16 m16n8k16, fp32 accumulate
__device__ __forceinline__ void mma_f16(float c[4], const uint32_t a[4],
                                        const uint32_t b[2]) {
    asm volatile(
        "mma.sync.aligned.m16n8k16.row.col.f32.f16.f16.f32 "
        "{%0,%1,%2,%3}, {%4,%5,%6,%7}, {%8,%9}, {%0,%1,%2,%3};"
        : "+f"(c[0]), "+f"(c[1]), "+f"(c[2]), "+f"(c[3])
        : "r"(a[0]), "r"(a[1]), "r"(a[2]), "r"(a[3]), "r"(b[0]), "r"(b[1]));
}

// Smem geometry: K-chunk 64 halves = 32 words/row, padded to 36 words (144B).
// Fragment bank check: addr word = r*36 + kk, r = base+gid, kk = ks*8+tig
//   bank = (4*gid + tig + const) mod 32 -> 32 distinct lanes. Conflict-free.
#define ROWW     36                         // words per row
#define TILE_BYTES (128 * ROWW * 4)         // 18432
#define STAGE    (2 * TILE_BYTES)           // 36864 (A + B)
#define NSTG     3
#define GSMEM_BYTES (NSTG * STAGE + 1024)   // 111616 -> 2 CTA/SM

// ---------------------------------------------------------------------------
// Pre-pass: fp32 -> fp16, vectorized (float4 -> 4 halves).
// ---------------------------------------------------------------------------
__global__ void conv_h_kernel(const float4* __restrict__ src,
                              uint2* __restrict__ dst, int n4)
{
    for (int i = blockIdx.x * blockDim.x + threadIdx.x; i < n4;
         i += gridDim.x * blockDim.x) {
        float4 v = src[i];
        __half2 a = __floats2half2_rn(v.x, v.y);
        __half2 b = __floats2half2_rn(v.z, v.w);
        uint2 u;
        u.x = *reinterpret_cast<const uint32_t*>(&a);
        u.y = *reinterpret_cast<const uint32_t*>(&b);
        dst[i] = u;
    }
}

// ---------------------------------------------------------------------------
// GEMM inner chunk (K=64): 4 ks-steps of m16n8k16.
// Warp tile 64x32: mWarp=(w&1)*64, nWarp=(w>>1)*32. c[4][4][4].
// ---------------------------------------------------------------------------
#define GEMM_COMPUTE_CHUNK(sA, sB)                                          \
    {                                                                       \
        _Pragma("unroll")                                                   \
        for (int ks = 0; ks < 4; ks++) {                                    \
            const int kk = ks * 8 + tig;                                    \
            uint32_t af[4][4];                                              \
            _Pragma("unroll")                                               \
            for (int mi = 0; mi < 4; mi++) {                                \
                const int r = mWarp + mi * 16 + gid;                        \
                af[mi][0] = sA[(r)     * ROWW + kk];                        \
                af[mi][1] = sA[(r + 8) * ROWW + kk];                        \
                af[mi][2] = sA[(r)     * ROWW + kk + 4];                    \
                af[mi][3] = sA[(r + 8) * ROWW + kk + 4];                    \
            }                                                               \
            uint32_t bf[4][2];                                              \
            _Pragma("unroll")                                               \
            for (int ni = 0; ni < 4; ni++) {                                \
                const int nn = nWarp + ni * 8 + gid;                        \
                bf[ni][0] = sB[nn * ROWW + kk];                             \
                bf[ni][1] = sB[nn * ROWW + kk + 4];                         \
            }                                                               \
            _Pragma("unroll")                                               \
            for (int mi = 0; mi < 4; mi++)                                  \
                _Pragma("unroll")                                           \
                for (int ni = 0; ni < 4; ni++)                              \
                    mma_f16(c[mi][ni], af[mi], bf[ni]);                     \
        }                                                                   \
    }

#define PIPE_WAIT(ch) { if ((ch) < 3) cp_wait1(); else cp_wait0(); }

// ---------------------------------------------------------------------------
// Kernel 1: K or V projection. grid (2, 2, 1536): x=N-tile, y=K/V, z=M-tile.
//   (x,y fastest -> the 4 CTAs sharing the same X rows run adjacently: L2 reuse)
// ---------------------------------------------------------------------------
__global__ void __launch_bounds__(256, 2)
kv_mma_kernel(const float* __restrict__ bk, const float* __restrict__ bv)
{
    extern __shared__ char smem[];
    const __half* W    = (blockIdx.y == 0) ? g_wkh : g_wvh;
    const float*  bias = (blockIdx.y == 0) ? bk : bv;
    __half*       dst  = (blockIdx.y == 0) ? g_k : g_v;

    const int tid  = threadIdx.x;
    const int w    = tid >> 5, lane = tid & 31;
    const int gid  = lane >> 2, tig = lane & 3;
    const int mWarp = (w & 1) * 64;
    const int nWarp = (w >> 1) * 32;
    const int colBase = blockIdx.x * 128;
    const int rowBase = blockIdx.z * 128;
    const uint32_t sb = smem_u32(smem);

    float* sbias = (float*)(smem + NSTG * STAGE);
    if (tid < 128) sbias[tid] = bias[colBase + tid];

    float c[4][4][4];
#pragma unroll
    for (int mi = 0; mi < 4; mi++)
#pragma unroll
        for (int ni = 0; ni < 4; ni++)
#pragma unroll
            for (int j = 0; j < 4; j++) c[mi][ni][j] = 0.f;

    auto load_stage = [&](int ch) {
        const int s = ch % NSTG;
        const int k0 = ch * 64;                         // halves
        const uint32_t aBase = sb + s * STAGE;
        const uint32_t bBase = aBase + TILE_BYTES;
#pragma unroll
        for (int j = 0; j < 4; j++) {                   // 1024 16B copies each
            const int e = tid + 256 * j;
            const int r = e >> 3, cc = e & 7;           // 8 x 16B per 128B row
            const uint32_t soff = (uint32_t)(r * 144 + cc * 16);
            cp_async16(aBase + soff,
                       g_xh + (size_t)(rowBase + r) * D_ + k0 + cc * 8);
            cp_async16(bBase + soff,
                       W + (size_t)(colBase + r) * D_ + k0 + cc * 8);
        }
    };

    load_stage(0); cp_commit();
    load_stage(1); cp_commit();

    for (int ch = 0; ch < 4; ch++) {
        PIPE_WAIT(ch);
        __syncthreads();
        if (ch + 2 < 4) { load_stage(ch + 2); cp_commit(); }
        const uint32_t* sA = (const uint32_t*)(smem + (ch % NSTG) * STAGE);
        const uint32_t* sB = (const uint32_t*)(smem + (ch % NSTG) * STAGE + TILE_BYTES);
        GEMM_COMPUTE_CHUNK(sA, sB);
    }

#pragma unroll
    for (int mi = 0; mi < 4; mi++) {
        const int r0 = rowBase + mWarp + mi * 16 + gid;
#pragma unroll
        for (int rr = 0; rr < 2; rr++) {
            const int m = r0 + rr * 8;
            const int tb = m / N_, n = m - tb * N_;
#pragma unroll
            for (int ni = 0; ni < 4; ni++) {
                const int oc = nWarp + ni * 8 + tig * 2;
                const int o = colBase + oc;
                const int h = o >> 5, f = o & 31;
                __half2 v = __floats2half2_rn(c[mi][ni][2 * rr + 0] + sbias[oc],
                                              c[mi][ni][2 * rr + 1] + sbias[oc + 1]);
                *(__half2*)&dst[(((size_t)tb * H_ + h) * N_ + n) * F_ + f] = v;
            }
        }
    }
}

// ---------------------------------------------------------------------------
// Kernel 2: Q projection. grid (2, 24, 64): x=N-tile, y=joint, z=tb-tile.
// ---------------------------------------------------------------------------
__global__ void __launch_bounds__(256, 2)
q_mma_kernel(const float* __restrict__ bq)
{
    extern __shared__ char smem[];
    const int nJ = blockIdx.y;

    const int tid  = threadIdx.x;
    const int w    = tid >> 5, lane = tid & 31;
    const int gid  = lane >> 2, tig = lane & 3;
    const int mWarp = (w & 1) * 64;
    const int nWarp = (w >> 1) * 32;
    const int colBase = blockIdx.x * 128;
    const int rowBase = blockIdx.z * 128;
    const uint32_t sb = smem_u32(smem);

    float* sbias = (float*)(smem + NSTG * STAGE);
    if (tid < 128) {
        const int o = colBase + tid;
        const int h = o >> 5, f = o & 31;
        sbias[tid] = bq[(h * N_ + nJ) * F_ + f];
    }

    float c[4][4][4];
#pragma unroll
    for (int mi = 0; mi < 4; mi++)
#pragma unroll
        for (int ni = 0; ni < 4; ni++)
#pragma unroll
            for (int j = 0; j < 4; j++) c[mi][ni][j] = 0.f;

    auto load_stage = [&](int ch) {
        const int s = ch % NSTG;
        const int k0 = ch * 64;
        const uint32_t aBase = sb + s * STAGE;
        const uint32_t bBase = aBase + TILE_BYTES;
#pragma unroll
        for (int j = 0; j < 4; j++) {
            const int e = tid + 256 * j;
            const int r = e >> 3, cc = e & 7;
            const uint32_t soff = (uint32_t)(r * 144 + cc * 16);
            cp_async16(aBase + soff,
                       g_xh + (size_t)(rowBase + r) * ND_ + nJ * D_ + k0 + cc * 8);
            const int o = colBase + r;
            const int h = o >> 5, f = o & 31;
            cp_async16(bBase + soff,
                       g_wqh + ((size_t)(h * N_ + nJ) * F_ + f) * D_ + k0 + cc * 8);
        }
    };

    load_stage(0); cp_commit();
    load_stage(1); cp_commit();

    for (int ch = 0; ch < 4; ch++) {
        PIPE_WAIT(ch);
        __syncthreads();
        if (ch + 2 < 4) { load_stage(ch + 2); cp_commit(); }
        const uint32_t* sA = (const uint32_t*)(smem + (ch % NSTG) * STAGE);
        const uint32_t* sB = (const uint32_t*)(smem + (ch % NSTG) * STAGE + TILE_BYTES);
        GEMM_COMPUTE_CHUNK(sA, sB);
    }

#pragma unroll
    for (int mi = 0; mi < 4; mi++) {
        const int r0 = rowBase + mWarp + mi * 16 + gid;
#pragma unroll
        for (int rr = 0; rr < 2; rr++) {
            const int tb = r0 + rr * 8;
#pragma unroll
            for (int ni = 0; ni < 4; ni++) {
                const int oc = nWarp + ni * 8 + tig * 2;
                const int o = colBase + oc;
                const int h = o >> 5, f = o & 31;
                __half2 v = __floats2half2_rn(c[mi][ni][2 * rr + 0] + sbias[oc],
                                              c[mi][ni][2 * rr + 1] + sbias[oc + 1]);
                *(__half2*)&g_q[(((size_t)tb * H_ + h) * N_ + nJ) * F_ + f] = v;
            }
        }
    }
}

// ---------------------------------------------------------------------------
// Kernel 3: attention, lane-owns-row, fp16 inputs. 1 warp per (tb, h).
// ---------------------------------------------------------------------------
__global__ __launch_bounds__(128)
void attn_kernel(float* __restrict__ out)
{
    __shared__ float  sq[4][N_][33];     // q rows (fp32); reused as sout
    __shared__ float4 sk4[4][N_][9];     // k rows as float4
    __shared__ float4 sv4[4][N_][9];     // v rows as float4

    const int tb   = blockIdx.x;
    const int w    = threadIdx.x >> 5;
    const int lane = threadIdx.x & 31;
    const int h    = blockIdx.y * 4 + w;

    const size_t base = ((size_t)(tb * H_ + h)) * N_ * F_;
    const __half* qb = g_q + base;
    const __half* kb = g_k + base;
    const __half* vb = g_v + base;

    // q: half2 -> two floats
    for (int i = lane; i < N_ * F_ / 2; i += 32) {
        const __half2 hv = ((const __half2*)qb)[i];
        const float2 fv = __half22float2(hv);
        const int r = i >> 4, c2 = (i & 15) * 2;
        sq[w][r][c2] = fv.x; sq[w][r][c2 + 1] = fv.y;
    }
    // k, v: uint2 (4 halves) -> float4
    for (int i = lane; i < N_ * 8; i += 32) {
        const int r = i >> 3, cc = i & 7;
        uint2 ku = ((const uint2*)kb)[i];
        uint2 vu = ((const uint2*)vb)[i];
        float2 k01 = __half22float2(*(__half2*)&ku.x);
        float2 k23 = __half22float2(*(__half2*)&ku.y);
        float2 v01 = __half22float2(*(__half2*)&vu.x);
        float2 v23 = __half22float2(*(__half2*)&vu.y);
        sk4[w][r][cc] = make_float4(k01.x, k01.y, k23.x, k23.y);
        sv4[w][r][cc] = make_float4(v01.x, v01.y, v23.x, v23.y);
    }
    __syncwarp();

    const float scale = 0.17677669529663687f;  // 1/sqrt(32)

    float p[N_];
    if (lane < N_) {
        float q[F_];
#pragma unroll
        for (int f = 0; f < F_; f++) q[f] = sq[w][lane][f];

#pragma unroll
        for (int m = 0; m < N_; m++) {
            float acc = 0.f;
#pragma unroll
            for (int cc = 0; cc < 8; cc++) {
                float4 k4 = sk4[w][m][cc];
                acc += q[4 * cc + 0] * k4.x + q[4 * cc + 1] * k4.y
                     + q[4 * cc + 2] * k4.z + q[4 * cc + 3] * k4.w;
            }
            p[m] = acc * scale;
        }
        float mx = p[0];
#pragma unroll
        for (int m = 1; m < N_; m++) mx = fmaxf(mx, p[m]);
        float sum = 0.f;
#pragma unroll
        for (int m = 0; m < N_; m++) { p[m] = __expf(p[m] - mx); sum += p[m]; }
        const float inv = __frcp_rn(sum);
#pragma unroll
        for (int m = 0; m < N_; m++) p[m] *= inv;
    }
    __syncwarp();   // q reads done; sq becomes sout

    if (lane < N_) {
#pragma unroll
        for (int cc = 0; cc < 8; cc++) {
            float4 acc = make_float4(0.f, 0.f, 0.f, 0.f);
#pragma unroll
            for (int m = 0; m < N_; m++) {
                float4 v4 = sv4[w][m][cc];
                acc.x += p[m] * v4.x;  acc.y += p[m] * v4.y;
                acc.z += p[m] * v4.z;  acc.w += p[m] * v4.w;
            }
            sq[w][lane][4 * cc + 0] = acc.x;
            sq[w][lane][4 * cc + 1] = acc.y;
            sq[w][lane][4 * cc + 2] = acc.z;
            sq[w][lane][4 * cc + 3] = acc.w;
        }
    }
    __syncwarp();

    for (int i = lane; i < N_ * F_; i += 32) {
        const int n = i >> 5, f = i & 31;
        out[(size_t)tb * OUTW_ + (n * H_ + h) * F_ + f] = sq[w][n][f];
    }
}

// ---------------------------------------------------------------------------
extern "C" void kernel_launch(void* const* d_in, const int* in_sizes, int n_in,
                              void* d_out, int out_size)
{
    const float* x  = (const float*)d_in[0];
    const float* Wk = (const float*)d_in[1];
    const float* bk = (const float*)d_in[2];
    const float* Wv = (const float*)d_in[3];
    const float* bv = (const float*)d_in[4];
    const float* Wq = (const float*)d_in[5];
    const float* bq = (const float*)d_in[6];
    float* out = (float*)d_out;

    cudaFuncSetAttribute(kv_mma_kernel,
                         cudaFuncAttributeMaxDynamicSharedMemorySize, GSMEM_BYTES);
    cudaFuncSetAttribute(q_mma_kernel,
                         cudaFuncAttributeMaxDynamicSharedMemorySize, GSMEM_BYTES);

    void* xh; void* wkh; void* wvh; void* wqh;
    cudaGetSymbolAddress(&xh,  g_xh);
    cudaGetSymbolAddress(&wkh, g_wkh);
    cudaGetSymbolAddress(&wvh, g_wvh);
    cudaGetSymbolAddress(&wqh, g_wqh);

    // Pre-pass: fp32 -> fp16 once.
    conv_h_kernel<<<8192, 256>>>((const float4*)x,  (uint2*)xh,  TB_ * ND_ / 4);
    conv_h_kernel<<<64,   256>>>((const float4*)Wk, (uint2*)wkh, HF_ * D_ / 4);
    conv_h_kernel<<<64,   256>>>((const float4*)Wv, (uint2*)wvh, HF_ * D_ / 4);
    conv_h_kernel<<<1536, 256>>>((const float4*)Wq, (uint2*)wqh, H_ * N_ * F_ * D_ / 4);

    dim3 g1(2, 2, M1_ / 128);
    kv_mma_kernel<<<g1, 256, GSMEM_BYTES>>>(bk, bv);

    dim3 g2(2, N_, TB_ / 128);
    q_mma_kernel<<<g2, 256, GSMEM_BYTES>>>(bq);

    dim3 g3(TB_, 2);
    attn_kernel<<<g3, 128>>>(out);
}

// round 11
// speedup vs baseline: 1.9037x; 1.4327x over previous
#include <cuda_runtime.h>
#include <cuda_fp16.h>
#include <cstdint>
#include <math.h>

// Problem constants
#define T_    128
#define B_    64
#define TB_   8192      // T*B
#define N_    24        // joints
#define D_    256
#define H_    8
#define F_    32
#define HF_   256       // H*F
#define ND_   6144      // N*D
#define OUTW_ 6144      // N*H*F
#define M1_   196608    // TB*N rows for KV gemm

// fp16 scratch
__device__ __half g_q[TB_ * H_ * N_ * F_];
__device__ __half g_k[TB_ * H_ * N_ * F_];
__device__ __half g_v[TB_ * H_ * N_ * F_];
// fp16 copies of inputs (pre-converted once)
__device__ __half g_xh[TB_ * ND_];            // X   (100 MB)
__device__ __half g_wkh[HF_ * D_];
__device__ __half g_wvh[HF_ * D_];
__device__ __half g_wqh[H_ * N_ * F_ * D_];

// ---------------------------------------------------------------------------
// helpers
// ---------------------------------------------------------------------------
__device__ __forceinline__ uint32_t smem_u32(const void* p) {
    uint32_t a;
    asm("{ .reg .u64 t; cvta.to.shared.u64 t, %1; cvt.u32.u64 %0, t; }"
        : "=r"(a) : "l"(p));
    return a;
}
__device__ __forceinline__ void cp_async16(uint32_t dst, const void* src) {
    asm volatile("cp.async.cg.shared.global [%0], [%1], 16;"
                 :: "r"(dst), "l"(src) : "memory");
}
__device__ __forceinline__ void cp_commit() {
    asm volatile("cp.async.commit_group;" ::: "memory");
}
__device__ __forceinline__ void cp_wait1() {
    asm volatile("cp.async.wait_group 1;" ::: "memory");
}
__device__ __forceinline__ void cp_wait0() {
    asm volatile("cp.async.wait_group 0;" ::: "memory");
}
// fp16 m16n8k16, fp32 accumulate
__device__ __forceinline__ void mma_f16(float c[4], const uint32_t a[4],
                                        const uint32_t b[2]) {
    asm volatile(
        "mma.sync.aligned.m16n8k16.row.col.f32.f16.f16.f32 "
        "{%0,%1,%2,%3}, {%4,%5,%6,%7}, {%8,%9}, {%0,%1,%2,%3};"
        : "+f"(c[0]), "+f"(c[1]), "+f"(c[2]), "+f"(c[3])
        : "r"(a[0]), "r"(a[1]), "r"(a[2]), "r"(a[3]), "r"(b[0]), "r"(b[1]));
}
__device__ __forceinline__ uint32_t packh2(float x, float y) {
    __half2 h = __floats2half2_rn(x, y);
    return *reinterpret_cast<uint32_t*>(&h);
}

// Smem geometry (GEMMs): K-chunk 64 halves = 32 words/row, padded to 36 words.
#define ROWW     36                         // words per row
#define TILE_BYTES (128 * ROWW * 4)         // 18432
#define STAGE    (2 * TILE_BYTES)           // 36864 (A + B)
#define NSTG     3
#define GSMEM_BYTES (NSTG * STAGE + 1024)   // 111616 -> 2 CTA/SM

// ---------------------------------------------------------------------------
// Pre-pass: fp32 -> fp16, vectorized.
// ---------------------------------------------------------------------------
__global__ void conv_h_kernel(const float4* __restrict__ src,
                              uint2* __restrict__ dst, int n4)
{
    for (int i = blockIdx.x * blockDim.x + threadIdx.x; i < n4;
         i += gridDim.x * blockDim.x) {
        float4 v = src[i];
        __half2 a = __floats2half2_rn(v.x, v.y);
        __half2 b = __floats2half2_rn(v.z, v.w);
        uint2 u;
        u.x = *reinterpret_cast<const uint32_t*>(&a);
        u.y = *reinterpret_cast<const uint32_t*>(&b);
        dst[i] = u;
    }
}

// ---------------------------------------------------------------------------
// GEMM inner chunk (K=64): 4 ks-steps of m16n8k16. (unchanged, validated)
// ---------------------------------------------------------------------------
#define GEMM_COMPUTE_CHUNK(sA, sB)                                          \
    {                                                                       \
        _Pragma("unroll")                                                   \
        for (int ks = 0; ks < 4; ks++) {                                    \
            const int kk = ks * 8 + tig;                                    \
            uint32_t af[4][4];                                              \
            _Pragma("unroll")                                               \
            for (int mi = 0; mi < 4; mi++) {                                \
                const int r = mWarp + mi * 16 + gid;                        \
                af[mi][0] = sA[(r)     * ROWW + kk];                        \
                af[mi][1] = sA[(r + 8) * ROWW + kk];                        \
                af[mi][2] = sA[(r)     * ROWW + kk + 4];                    \
                af[mi][3] = sA[(r + 8) * ROWW + kk + 4];                    \
            }                                                               \
            uint32_t bf[4][2];                                              \
            _Pragma("unroll")                                               \
            for (int ni = 0; ni < 4; ni++) {                                \
                const int nn = nWarp + ni * 8 + gid;                        \
                bf[ni][0] = sB[nn * ROWW + kk];                             \
                bf[ni][1] = sB[nn * ROWW + kk + 4];                         \
            }                                                               \
            _Pragma("unroll")                                               \
            for (int mi = 0; mi < 4; mi++)                                  \
                _Pragma("unroll")                                           \
                for (int ni = 0; ni < 4; ni++)                              \
                    mma_f16(c[mi][ni], af[mi], bf[ni]);                     \
        }                                                                   \
    }

#define PIPE_WAIT(ch) { if ((ch) < 3) cp_wait1(); else cp_wait0(); }

// ---------------------------------------------------------------------------
// Kernel 1: K or V projection. grid (2, 2, 1536). (unchanged from R10)
// ---------------------------------------------------------------------------
__global__ void __launch_bounds__(256, 2)
kv_mma_kernel(const float* __restrict__ bk, const float* __restrict__ bv)
{
    extern __shared__ char smem[];
    const __half* W    = (blockIdx.y == 0) ? g_wkh : g_wvh;
    const float*  bias = (blockIdx.y == 0) ? bk : bv;
    __half*       dst  = (blockIdx.y == 0) ? g_k : g_v;

    const int tid  = threadIdx.x;
    const int w    = tid >> 5, lane = tid & 31;
    const int gid  = lane >> 2, tig = lane & 3;
    const int mWarp = (w & 1) * 64;
    const int nWarp = (w >> 1) * 32;
    const int colBase = blockIdx.x * 128;
    const int rowBase = blockIdx.z * 128;
    const uint32_t sb = smem_u32(smem);

    float* sbias = (float*)(smem + NSTG * STAGE);
    if (tid < 128) sbias[tid] = bias[colBase + tid];

    float c[4][4][4];
#pragma unroll
    for (int mi = 0; mi < 4; mi++)
#pragma unroll
        for (int ni = 0; ni < 4; ni++)
#pragma unroll
            for (int j = 0; j < 4; j++) c[mi][ni][j] = 0.f;

    auto load_stage = [&](int ch) {
        const int s = ch % NSTG;
        const int k0 = ch * 64;
        const uint32_t aBase = sb + s * STAGE;
        const uint32_t bBase = aBase + TILE_BYTES;
#pragma unroll
        for (int j = 0; j < 4; j++) {
            const int e = tid + 256 * j;
            const int r = e >> 3, cc = e & 7;
            const uint32_t soff = (uint32_t)(r * 144 + cc * 16);
            cp_async16(aBase + soff,
                       g_xh + (size_t)(rowBase + r) * D_ + k0 + cc * 8);
            cp_async16(bBase + soff,
                       W + (size_t)(colBase + r) * D_ + k0 + cc * 8);
        }
    };

    load_stage(0); cp_commit();
    load_stage(1); cp_commit();

    for (int ch = 0; ch < 4; ch++) {
        PIPE_WAIT(ch);
        __syncthreads();
        if (ch + 2 < 4) { load_stage(ch + 2); cp_commit(); }
        const uint32_t* sA = (const uint32_t*)(smem + (ch % NSTG) * STAGE);
        const uint32_t* sB = (const uint32_t*)(smem + (ch % NSTG) * STAGE + TILE_BYTES);
        GEMM_COMPUTE_CHUNK(sA, sB);
    }

#pragma unroll
    for (int mi = 0; mi < 4; mi++) {
        const int r0 = rowBase + mWarp + mi * 16 + gid;
#pragma unroll
        for (int rr = 0; rr < 2; rr++) {
            const int m = r0 + rr * 8;
            const int tb = m / N_, n = m - tb * N_;
#pragma unroll
            for (int ni = 0; ni < 4; ni++) {
                const int oc = nWarp + ni * 8 + tig * 2;
                const int o = colBase + oc;
                const int h = o >> 5, f = o & 31;
                __half2 v = __floats2half2_rn(c[mi][ni][2 * rr + 0] + sbias[oc],
                                              c[mi][ni][2 * rr + 1] + sbias[oc + 1]);
                *(__half2*)&dst[(((size_t)tb * H_ + h) * N_ + n) * F_ + f] = v;
            }
        }
    }
}

// ---------------------------------------------------------------------------
// Kernel 2: Q projection. grid (2, 24, 64). (unchanged from R10)
// ---------------------------------------------------------------------------
__global__ void __launch_bounds__(256, 2)
q_mma_kernel(const float* __restrict__ bq)
{
    extern __shared__ char smem[];
    const int nJ = blockIdx.y;

    const int tid  = threadIdx.x;
    const int w    = tid >> 5, lane = tid & 31;
    const int gid  = lane >> 2, tig = lane & 3;
    const int mWarp = (w & 1) * 64;
    const int nWarp = (w >> 1) * 32;
    const int colBase = blockIdx.x * 128;
    const int rowBase = blockIdx.z * 128;
    const uint32_t sb = smem_u32(smem);

    float* sbias = (float*)(smem + NSTG * STAGE);
    if (tid < 128) {
        const int o = colBase + tid;
        const int h = o >> 5, f = o & 31;
        sbias[tid] = bq[(h * N_ + nJ) * F_ + f];
    }

    float c[4][4][4];
#pragma unroll
    for (int mi = 0; mi < 4; mi++)
#pragma unroll
        for (int ni = 0; ni < 4; ni++)
#pragma unroll
            for (int j = 0; j < 4; j++) c[mi][ni][j] = 0.f;

    auto load_stage = [&](int ch) {
        const int s = ch % NSTG;
        const int k0 = ch * 64;
        const uint32_t aBase = sb + s * STAGE;
        const uint32_t bBase = aBase + TILE_BYTES;
#pragma unroll
        for (int j = 0; j < 4; j++) {
            const int e = tid + 256 * j;
            const int r = e >> 3, cc = e & 7;
            const uint32_t soff = (uint32_t)(r * 144 + cc * 16);
            cp_async16(aBase + soff,
                       g_xh + (size_t)(rowBase + r) * ND_ + nJ * D_ + k0 + cc * 8);
            const int o = colBase + r;
            const int h = o >> 5, f = o & 31;
            cp_async16(bBase + soff,
                       g_wqh + ((size_t)(h * N_ + nJ) * F_ + f) * D_ + k0 + cc * 8);
        }
    };

    load_stage(0); cp_commit();
    load_stage(1); cp_commit();

    for (int ch = 0; ch < 4; ch++) {
        PIPE_WAIT(ch);
        __syncthreads();
        if (ch + 2 < 4) { load_stage(ch + 2); cp_commit(); }
        const uint32_t* sA = (const uint32_t*)(smem + (ch % NSTG) * STAGE);
        const uint32_t* sB = (const uint32_t*)(smem + (ch % NSTG) * STAGE + TILE_BYTES);
        GEMM_COMPUTE_CHUNK(sA, sB);
    }

#pragma unroll
    for (int mi = 0; mi < 4; mi++) {
        const int r0 = rowBase + mWarp + mi * 16 + gid;
#pragma unroll
        for (int rr = 0; rr < 2; rr++) {
            const int tb = r0 + rr * 8;
#pragma unroll
            for (int ni = 0; ni < 4; ni++) {
                const int oc = nWarp + ni * 8 + tig * 2;
                const int o = colBase + oc;
                const int h = o >> 5, f = o & 31;
                __half2 v = __floats2half2_rn(c[mi][ni][2 * rr + 0] + sbias[oc],
                                              c[mi][ni][2 * rr + 1] + sbias[oc + 1]);
                *(__half2*)&g_q[(((size_t)tb * H_ + h) * N_ + nJ) * F_ + f] = v;
            }
        }
    }
}

// ---------------------------------------------------------------------------
// Kernel 3: tensor-core attention. 1 warp per (tb,h), grid (TB, 2) x 128.
//   S = Q K^T via m16n8k16 (M=24 pad 32, N=24, K=32), softmax on fragments,
//   C-frag == A-frag identity feeds P (packed to fp16 in regs) into O = P V.
//   Smem per warp: q[32r x 20w], k[32r x 20w], vT[32r(f) x 20w(m)].
// ---------------------------------------------------------------------------
#define AROW 20   // words per smem row (conflict-free: 20*gid+tig distinct)

__global__ __launch_bounds__(128)
void attn_kernel(float* __restrict__ out)
{
    __shared__ uint32_t sm[4][3][32 * AROW];

    const int tb   = blockIdx.x;
    const int w    = threadIdx.x >> 5;
    const int lane = threadIdx.x & 31;
    const int gid  = lane >> 2, tig = lane & 3;
    const int h    = blockIdx.y * 4 + w;

    uint32_t* qs = sm[w][0];
    uint32_t* ks = sm[w][1];
    uint32_t* vs = sm[w][2];

    const size_t base = ((size_t)(tb * H_ + h)) * N_ * F_;
    const uint2* qg = (const uint2*)(g_q + base);
    const uint2* kg = (const uint2*)(g_k + base);
    const uint2* vg = (const uint2*)(g_v + base);

    // stage q, k: 24 rows x 8 uint2 (16 words) at row stride AROW
    for (int i = lane; i < 24 * 8; i += 32) {
        const int r = i >> 3, cc = i & 7;
        *(uint2*)&qs[r * AROW + cc * 2] = qg[i];
        *(uint2*)&ks[r * AROW + cc * 2] = kg[i];
    }
    // stage v TRANSPOSED: vs[f][m] halves (row stride 2*AROW halves)
    __half* vsh = (__half*)vs;
    for (int i = lane; i < 24 * 8; i += 32) {
        const int m = i >> 3, cc = i & 7;
        uint2 u = vg[i];
        __half2 h01 = *(__half2*)&u.x, h23 = *(__half2*)&u.y;
        const int f0 = cc * 4;
        vsh[(f0 + 0) * (2 * AROW) + m] = __low2half(h01);
        vsh[(f0 + 1) * (2 * AROW) + m] = __high2half(h01);
        vsh[(f0 + 2) * (2 * AROW) + m] = __low2half(h23);
        vsh[(f0 + 3) * (2 * AROW) + m] = __high2half(h23);
    }
    // zero vT pad cols m=24..31 (avoid NaN*0 in HMMA): lane -> f row
    *(uint4*)&vsh[lane * (2 * AROW) + 24] = make_uint4(0, 0, 0, 0);
    __syncwarp();

    // ---- S = Q K^T : c[mi][ni][4], mi over M (2x16), ni over N (3x8) ----
    float cs[2][3][4];
#pragma unroll
    for (int mi = 0; mi < 2; mi++)
#pragma unroll
        for (int ni = 0; ni < 3; ni++)
#pragma unroll
            for (int j = 0; j < 4; j++) cs[mi][ni][j] = 0.f;

#pragma unroll
    for (int kb = 0; kb < 2; kb++) {
        uint32_t a[2][4];
#pragma unroll
        for (int mi = 0; mi < 2; mi++) {
            const int r = mi * 16 + gid;
            a[mi][0] = qs[(r)     * AROW + kb * 8 + tig];
            a[mi][1] = qs[(r + 8) * AROW + kb * 8 + tig];
            a[mi][2] = qs[(r)     * AROW + kb * 8 + tig + 4];
            a[mi][3] = qs[(r + 8) * AROW + kb * 8 + tig + 4];
        }
#pragma unroll
        for (int ni = 0; ni < 3; ni++) {
            uint32_t b[2];
            b[0] = ks[(ni * 8 + gid) * AROW + kb * 8 + tig];
            b[1] = ks[(ni * 8 + gid) * AROW + kb * 8 + tig + 4];
#pragma unroll
            for (int mi = 0; mi < 2; mi++) mma_f16(cs[mi][ni], a[mi], b);
        }
    }

    // ---- softmax over the 24 columns (per row; rows live in tig-quads) ----
    const float scale = 0.17677669529663687f;  // 1/sqrt(32)
    float p[2][3][4];
#pragma unroll
    for (int mi = 0; mi < 2; mi++) {
        float m0 = -1e30f, m1 = -1e30f;
#pragma unroll
        for (int ni = 0; ni < 3; ni++) {
            m0 = fmaxf(m0, fmaxf(cs[mi][ni][0], cs[mi][ni][1]));
            m1 = fmaxf(m1, fmaxf(cs[mi][ni][2], cs[mi][ni][3]));
        }
        m0 = fmaxf(m0, __shfl_xor_sync(0xffffffffu, m0, 1));
        m0 = fmaxf(m0, __shfl_xor_sync(0xffffffffu, m0, 2));
        m1 = fmaxf(m1, __shfl_xor_sync(0xffffffffu, m1, 1));
        m1 = fmaxf(m1, __shfl_xor_sync(0xffffffffu, m1, 2));

        float s0 = 0.f, s1 = 0.f;
#pragma unroll
        for (int ni = 0; ni < 3; ni++) {
            p[mi][ni][0] = __expf((cs[mi][ni][0] - m0) * scale);
            p[mi][ni][1] = __expf((cs[mi][ni][1] - m0) * scale);
            p[mi][ni][2] = __expf((cs[mi][ni][2] - m1) * scale);
            p[mi][ni][3] = __expf((cs[mi][ni][3] - m1) * scale);
            s0 += p[mi][ni][0] + p[mi][ni][1];
            s1 += p[mi][ni][2] + p[mi][ni][3];
        }
        s0 += __shfl_xor_sync(0xffffffffu, s0, 1);
        s0 += __shfl_xor_sync(0xffffffffu, s0, 2);
        s1 += __shfl_xor_sync(0xffffffffu, s1, 1);
        s1 += __shfl_xor_sync(0xffffffffu, s1, 2);
        const float i0 = __frcp_rn(s0), i1 = __frcp_rn(s1);
#pragma unroll
        for (int ni = 0; ni < 3; ni++) {
            p[mi][ni][0] *= i0; p[mi][ni][1] *= i0;
            p[mi][ni][2] *= i1; p[mi][ni][3] *= i1;
        }
    }

    // ---- O = P V : P as A-fragments (C-frag == A-frag identity) ----
    float co[2][4][4];
#pragma unroll
    for (int mi = 0; mi < 2; mi++)
#pragma unroll
        for (int nj = 0; nj < 4; nj++)
#pragma unroll
            for (int j = 0; j < 4; j++) co[mi][nj][j] = 0.f;

#pragma unroll
    for (int mi = 0; mi < 2; mi++) {
        uint32_t ap0[4], ap1[4];
        ap0[0] = packh2(p[mi][0][0], p[mi][0][1]);
        ap0[1] = packh2(p[mi][0][2], p[mi][0][3]);
        ap0[2] = packh2(p[mi][1][0], p[mi][1][1]);
        ap0[3] = packh2(p[mi][1][2], p[mi][1][3]);
        ap1[0] = packh2(p[mi][2][0], p[mi][2][1]);
        ap1[1] = packh2(p[mi][2][2], p[mi][2][3]);
        ap1[2] = 0u; ap1[3] = 0u;
#pragma unroll
        for (int nj = 0; nj < 4; nj++) {
            uint32_t b0[2], b1[2];
            b0[0] = vs[(nj * 8 + gid) * AROW + tig];
            b0[1] = vs[(nj * 8 + gid) * AROW + tig + 4];
            b1[0] = vs[(nj * 8 + gid) * AROW + 8 + tig];
            b1[1] = vs[(nj * 8 + gid) * AROW + 8 + tig + 4];
            mma_f16(co[mi][nj], ap0, b0);   // keys 0..15
            mma_f16(co[mi][nj], ap1, b1);   // keys 16..23 (+pad)
        }
    }

    // ---- store: row n -> out[tb][(n*H+h)*F + f], float2 per (nj, half) ----
#pragma unroll
    for (int mi = 0; mi < 2; mi++) {
        const int r0 = mi * 16 + gid;
#pragma unroll
        for (int nj = 0; nj < 4; nj++) {
            const int fcol = nj * 8 + 2 * tig;
            float2 v0;
            v0.x = co[mi][nj][0]; v0.y = co[mi][nj][1];
            *(float2*)&out[(size_t)tb * OUTW_ + (r0 * H_ + h) * F_ + fcol] = v0;
            if (mi == 0) {                  // rows 8..15 (mi=1's +8 rows are pad)
                float2 v1;
                v1.x = co[mi][nj][2]; v1.y = co[mi][nj][3];
                *(float2*)&out[(size_t)tb * OUTW_ + ((r0 + 8) * H_ + h) * F_ + fcol] = v1;
            }
        }
    }
}

// ---------------------------------------------------------------------------
extern "C" void kernel_launch(void* const* d_in, const int* in_sizes, int n_in,
                              void* d_out, int out_size)
{
    const float* x  = (const float*)d_in[0];
    const float* Wk = (const float*)d_in[1];
    const float* bk = (const float*)d_in[2];
    const float* Wv = (const float*)d_in[3];
    const float* bv = (const float*)d_in[4];
    const float* Wq = (const float*)d_in[5];
    const float* bq = (const float*)d_in[6];
    float* out = (float*)d_out;

    cudaFuncSetAttribute(kv_mma_kernel,
                         cudaFuncAttributeMaxDynamicSharedMemorySize, GSMEM_BYTES);
    cudaFuncSetAttribute(q_mma_kernel,
                         cudaFuncAttributeMaxDynamicSharedMemorySize, GSMEM_BYTES);

    void* xh; void* wkh; void* wvh; void* wqh;
    cudaGetSymbolAddress(&xh,  g_xh);
    cudaGetSymbolAddress(&wkh, g_wkh);
    cudaGetSymbolAddress(&wvh, g_wvh);
    cudaGetSymbolAddress(&wqh, g_wqh);

    // Pre-pass: fp32 -> fp16 once.
    conv_h_kernel<<<8192, 256>>>((const float4*)x,  (uint2*)xh,  TB_ * ND_ / 4);
    conv_h_kernel<<<64,   256>>>((const float4*)Wk, (uint2*)wkh, HF_ * D_ / 4);
    conv_h_kernel<<<64,   256>>>((const float4*)Wv, (uint2*)wvh, HF_ * D_ / 4);
    conv_h_kernel<<<1536, 256>>>((const float4*)Wq, (uint2*)wqh, H_ * N_ * F_ * D_ / 4);

    dim3 g1(2, 2, M1_ / 128);
    kv_mma_kernel<<<g1, 256, GSMEM_BYTES>>>(bk, bv);

    dim3 g2(2, N_, TB_ / 128);
    q_mma_kernel<<<g2, 256, GSMEM_BYTES>>>(bq);

    dim3 g3(TB_, 2);
    attn_kernel<<<g3, 128>>>(out);
}

// round 14
// speedup vs baseline: 1.9108x; 1.0037x over previous
#include <cuda_runtime.h>
#include <cuda_fp16.h>
#include <cstdint>
#include <math.h>

// Problem constants
#define T_    128
#define B_    64
#define TB_   8192      // T*B
#define N_    24        // joints
#define D_    256
#define H_    8
#define F_    32
#define HF_   256       // H*F
#define ND_   6144      // N*D
#define OUTW_ 6144      // N*H*F
#define M1_   196608    // TB*N rows for KV gemm

// fp16 scratch
__device__ __half g_q[TB_ * H_ * N_ * F_];
__device__ __half g_k[TB_ * H_ * N_ * F_];
__device__ __half g_v[TB_ * H_ * N_ * F_];
// fp16 copies of inputs (pre-converted once)
__device__ __half g_xh[TB_ * ND_];            // X   (100 MB)
__device__ __half g_wkh[HF_ * D_];
__device__ __half g_wvh[HF_ * D_];
__device__ __half g_wqh[H_ * N_ * F_ * D_];

// ---------------------------------------------------------------------------
// helpers
// ---------------------------------------------------------------------------
__device__ __forceinline__ uint32_t smem_u32(const void* p) {
    uint32_t a;
    asm("{ .reg .u64 t; cvta.to.shared.u64 t, %1; cvt.u32.u64 %0, t; }"
        : "=r"(a) : "l"(p));
    return a;
}
__device__ __forceinline__ void cp_async16(uint32_t dst, const void* src) {
    asm volatile("cp.async.cg.shared.global [%0], [%1], 16;"
                 :: "r"(dst), "l"(src) : "memory");
}
__device__ __forceinline__ void cp_commit() {
    asm volatile("cp.async.commit_group;" ::: "memory");
}
__device__ __forceinline__ void cp_wait1() {
    asm volatile("cp.async.wait_group 1;" ::: "memory");
}
__device__ __forceinline__ void cp_wait0() {
    asm volatile("cp.async.wait_group 0;" ::: "memory");
}
// fp16 m16n8k16, fp32 accumulate
__device__ __forceinline__ void mma_f16(float c[4], const uint32_t a[4],
                                        const uint32_t b[2]) {
    asm volatile(
        "mma.sync.aligned.m16n8k16.row.col.f32.f16.f16.f32 "
        "{%0,%1,%2,%3}, {%4,%5,%6,%7}, {%8,%9}, {%0,%1,%2,%3};"
        : "+f"(c[0]), "+f"(c[1]), "+f"(c[2]), "+f"(c[3])
        : "r"(a[0]), "r"(a[1]), "r"(a[2]), "r"(a[3]), "r"(b[0]), "r"(b[1]));
}
__device__ __forceinline__ uint32_t packh2(float x, float y) {
    __half2 h = __floats2half2_rn(x, y);
    return *reinterpret_cast<uint32_t*>(&h);
}

// Smem geometry: K-chunk 64 halves = 32 words/row, padded to 36 words.
#define ROWW     36                         // words per row
#define TILE_BYTES (128 * ROWW * 4)         // 18432

// KV fused: stage = A + Bk + Bv
#define KV_STAGE   (3 * TILE_BYTES)         // 55296
#define KV_NSTG    3
#define KV_SMEM    (KV_NSTG * KV_STAGE + 1024)  // 166912 -> 1 CTA/SM

// Q: stage = A + B
#define Q_STAGE    (2 * TILE_BYTES)         // 36864
#define Q_NSTG     3
#define Q_SMEM     (Q_NSTG * Q_STAGE + 1024)    // 111616 -> 2 CTA/SM

// ---------------------------------------------------------------------------
// Pre-pass: fp32 -> fp16, vectorized.
// ---------------------------------------------------------------------------
__global__ void conv_h_kernel(const float4* __restrict__ src,
                              uint2* __restrict__ dst, int n4)
{
    for (int i = blockIdx.x * blockDim.x + threadIdx.x; i < n4;
         i += gridDim.x * blockDim.x) {
        float4 v = src[i];
        __half2 a = __floats2half2_rn(v.x, v.y);
        __half2 b = __floats2half2_rn(v.z, v.w);
        uint2 u;
        u.x = *reinterpret_cast<const uint32_t*>(&a);
        u.y = *reinterpret_cast<const uint32_t*>(&b);
        dst[i] = u;
    }
}

// ---------------------------------------------------------------------------
// Kernel 1: fused K+V projection. grid (2, 1536): x=N-tile, y=M-tile.
//   CTA computes C_K and C_V (128x128 each) sharing A-fragments.
// ---------------------------------------------------------------------------
__global__ void __launch_bounds__(256, 1)
kv_mma_kernel(const float* __restrict__ bk, const float* __restrict__ bv)
{
    extern __shared__ char smem[];
    const int tid  = threadIdx.x;
    const int w    = tid >> 5, lane = tid & 31;
    const int gid  = lane >> 2, tig = lane & 3;
    const int mWarp = (w & 1) * 64;
    const int nWarp = (w >> 1) * 32;
    const int colBase = blockIdx.x * 128;
    const int rowBase = blockIdx.y * 128;
    const uint32_t sb = smem_u32(smem);

    float* sbK = (float*)(smem + KV_NSTG * KV_STAGE);
    float* sbV = sbK + 128;
    if (tid < 128) { sbK[tid] = bk[colBase + tid]; sbV[tid] = bv[colBase + tid]; }

    float cK[4][4][4], cV[4][4][4];
#pragma unroll
    for (int mi = 0; mi < 4; mi++)
#pragma unroll
        for (int ni = 0; ni < 4; ni++)
#pragma unroll
            for (int j = 0; j < 4; j++) { cK[mi][ni][j] = 0.f; cV[mi][ni][j] = 0.f; }

    auto load_stage = [&](int ch) {
        const int s = ch % KV_NSTG;
        const int k0 = ch * 64;                 // halves
        const uint32_t aBase  = sb + s * KV_STAGE;
        const uint32_t bkBase = aBase + TILE_BYTES;
        const uint32_t bvBase = aBase + 2 * TILE_BYTES;
#pragma unroll
        for (int j = 0; j < 4; j++) {
            const int e = tid + 256 * j;
            const int r = e >> 3, cc = e & 7;   // 8 x 16B per 128B row
            const uint32_t soff = (uint32_t)(r * 144 + cc * 16);
            cp_async16(aBase + soff,
                       g_xh + (size_t)(rowBase + r) * D_ + k0 + cc * 8);
            cp_async16(bkBase + soff,
                       g_wkh + (size_t)(colBase + r) * D_ + k0 + cc * 8);
            cp_async16(bvBase + soff,
                       g_wvh + (size_t)(colBase + r) * D_ + k0 + cc * 8);
        }
    };

    load_stage(0); cp_commit();
    load_stage(1); cp_commit();

    for (int ch = 0; ch < 4; ch++) {
        if (ch < 3) cp_wait1(); else cp_wait0();
        __syncthreads();
        if (ch + 2 < 4) { load_stage(ch + 2); cp_commit(); }
        const uint32_t* sA  = (const uint32_t*)(smem + (ch % KV_NSTG) * KV_STAGE);
        const uint32_t* sBk = sA + TILE_BYTES / 4;
        const uint32_t* sBv = sA + 2 * TILE_BYTES / 4;
#pragma unroll
        for (int ks = 0; ks < 4; ks++) {
            const int kk = ks * 8 + tig;
            uint32_t af[4][4];
#pragma unroll
            for (int mi = 0; mi < 4; mi++) {
                const int r = mWarp + mi * 16 + gid;
                af[mi][0] = sA[(r)     * ROWW + kk];
                af[mi][1] = sA[(r + 8) * ROWW + kk];
                af[mi][2] = sA[(r)     * ROWW + kk + 4];
                af[mi][3] = sA[(r + 8) * ROWW + kk + 4];
            }
#pragma unroll
            for (int ni = 0; ni < 4; ni++) {
                const int nn = nWarp + ni * 8 + gid;
                uint32_t bK[2], bV[2];
                bK[0] = sBk[nn * ROWW + kk];
                bK[1] = sBk[nn * ROWW + kk + 4];
                bV[0] = sBv[nn * ROWW + kk];
                bV[1] = sBv[nn * ROWW + kk + 4];
#pragma unroll
                for (int mi = 0; mi < 4; mi++) {
                    mma_f16(cK[mi][ni], af[mi], bK);
                    mma_f16(cV[mi][ni], af[mi], bV);
                }
            }
        }
    }

#pragma unroll
    for (int mi = 0; mi < 4; mi++) {
        const int r0 = rowBase + mWarp + mi * 16 + gid;
#pragma unroll
        for (int rr = 0; rr < 2; rr++) {
            const int m = r0 + rr * 8;
            const int tb = m / N_, n = m - tb * N_;
#pragma unroll
            for (int ni = 0; ni < 4; ni++) {
                const int oc = nWarp + ni * 8 + tig * 2;
                const int o = colBase + oc;
                const int h = o >> 5, f = o & 31;
                const size_t idx = (((size_t)tb * H_ + h) * N_ + n) * F_ + f;
                __half2 vk = __floats2half2_rn(cK[mi][ni][2 * rr + 0] + sbK[oc],
                                               cK[mi][ni][2 * rr + 1] + sbK[oc + 1]);
                __half2 vv = __floats2half2_rn(cV[mi][ni][2 * rr + 0] + sbV[oc],
                                               cV[mi][ni][2 * rr + 1] + sbV[oc + 1]);
                *(__half2*)&g_k[idx] = vk;
                *(__half2*)&g_v[idx] = vv;
            }
        }
    }
}

// ---------------------------------------------------------------------------
// Kernel 2: Q projection. grid (2, 24, 64). (unchanged, validated)
// ---------------------------------------------------------------------------
__global__ void __launch_bounds__(256, 2)
q_mma_kernel(const float* __restrict__ bq)
{
    extern __shared__ char smem[];
    const int nJ = blockIdx.y;

    const int tid  = threadIdx.x;
    const int w    = tid >> 5, lane = tid & 31;
    const int gid  = lane >> 2, tig = lane & 3;
    const int mWarp = (w & 1) * 64;
    const int nWarp = (w >> 1) * 32;
    const int colBase = blockIdx.x * 128;
    const int rowBase = blockIdx.z * 128;
    const uint32_t sb = smem_u32(smem);

    float* sbias = (float*)(smem + Q_NSTG * Q_STAGE);
    if (tid < 128) {
        const int o = colBase + tid;
        const int h = o >> 5, f = o & 31;
        sbias[tid] = bq[(h * N_ + nJ) * F_ + f];
    }

    float c[4][4][4];
#pragma unroll
    for (int mi = 0; mi < 4; mi++)
#pragma unroll
        for (int ni = 0; ni < 4; ni++)
#pragma unroll
            for (int j = 0; j < 4; j++) c[mi][ni][j] = 0.f;

    auto load_stage = [&](int ch) {
        const int s = ch % Q_NSTG;
        const int k0 = ch * 64;
        const uint32_t aBase = sb + s * Q_STAGE;
        const uint32_t bBase = aBase + TILE_BYTES;
#pragma unroll
        for (int j = 0; j < 4; j++) {
            const int e = tid + 256 * j;
            const int r = e >> 3, cc = e & 7;
            const uint32_t soff = (uint32_t)(r * 144 + cc * 16);
            cp_async16(aBase + soff,
                       g_xh + (size_t)(rowBase + r) * ND_ + nJ * D_ + k0 + cc * 8);
            const int o = colBase + r;
            const int h = o >> 5, f = o & 31;
            cp_async16(bBase + soff,
                       g_wqh + ((size_t)(h * N_ + nJ) * F_ + f) * D_ + k0 + cc * 8);
        }
    };

    load_stage(0); cp_commit();
    load_stage(1); cp_commit();

    for (int ch = 0; ch < 4; ch++) {
        if (ch < 3) cp_wait1(); else cp_wait0();
        __syncthreads();
        if (ch + 2 < 4) { load_stage(ch + 2); cp_commit(); }
        const uint32_t* sA = (const uint32_t*)(smem + (ch % Q_NSTG) * Q_STAGE);
        const uint32_t* sB = sA + TILE_BYTES / 4;
#pragma unroll
        for (int ks = 0; ks < 4; ks++) {
            const int kk = ks * 8 + tig;
            uint32_t af[4][4];
#pragma unroll
            for (int mi = 0; mi < 4; mi++) {
                const int r = mWarp + mi * 16 + gid;
                af[mi][0] = sA[(r)     * ROWW + kk];
                af[mi][1] = sA[(r + 8) * ROWW + kk];
                af[mi][2] = sA[(r)     * ROWW + kk + 4];
                af[mi][3] = sA[(r + 8) * ROWW + kk + 4];
            }
            uint32_t bf[4][2];
#pragma unroll
            for (int ni = 0; ni < 4; ni++) {
                const int nn = nWarp + ni * 8 + gid;
                bf[ni][0] = sB[nn * ROWW + kk];
                bf[ni][1] = sB[nn * ROWW + kk + 4];
            }
#pragma unroll
            for (int mi = 0; mi < 4; mi++)
#pragma unroll
                for (int ni = 0; ni < 4; ni++)
                    mma_f16(c[mi][ni], af[mi], bf[ni]);
        }
    }

#pragma unroll
    for (int mi = 0; mi < 4; mi++) {
        const int r0 = rowBase + mWarp + mi * 16 + gid;
#pragma unroll
        for (int rr = 0; rr < 2; rr++) {
            const int tb = r0 + rr * 8;
#pragma unroll
            for (int ni = 0; ni < 4; ni++) {
                const int oc = nWarp + ni * 8 + tig * 2;
                const int o = colBase + oc;
                const int h = o >> 5, f = o & 31;
                __half2 v = __floats2half2_rn(c[mi][ni][2 * rr + 0] + sbias[oc],
                                              c[mi][ni][2 * rr + 1] + sbias[oc + 1]);
                *(__half2*)&g_q[(((size_t)tb * H_ + h) * N_ + nJ) * F_ + f] = v;
            }
        }
    }
}

// ---------------------------------------------------------------------------
// Kernel 3: tensor-core attention (unchanged from R11, validated).
// ---------------------------------------------------------------------------
#define AROW 20   // words per smem row (conflict-free)

__global__ __launch_bounds__(128)
void attn_kernel(float* __restrict__ out)
{
    __shared__ uint32_t sm[4][3][32 * AROW];

    const int tb   = blockIdx.x;
    const int w    = threadIdx.x >> 5;
    const int lane = threadIdx.x & 31;
    const int gid  = lane >> 2, tig = lane & 3;
    const int h    = blockIdx.y * 4 + w;

    uint32_t* qs = sm[w][0];
    uint32_t* ks = sm[w][1];
    uint32_t* vs = sm[w][2];

    const size_t base = ((size_t)(tb * H_ + h)) * N_ * F_;
    const uint2* qg = (const uint2*)(g_q + base);
    const uint2* kg = (const uint2*)(g_k + base);
    const uint2* vg = (const uint2*)(g_v + base);

    for (int i = lane; i < 24 * 8; i += 32) {
        const int r = i >> 3, cc = i & 7;
        *(uint2*)&qs[r * AROW + cc * 2] = qg[i];
        *(uint2*)&ks[r * AROW + cc * 2] = kg[i];
    }
    __half* vsh = (__half*)vs;
    for (int i = lane; i < 24 * 8; i += 32) {
        const int m = i >> 3, cc = i & 7;
        uint2 u = vg[i];
        __half2 h01 = *(__half2*)&u.x, h23 = *(__half2*)&u.y;
        const int f0 = cc * 4;
        vsh[(f0 + 0) * (2 * AROW) + m] = __low2half(h01);
        vsh[(f0 + 1) * (2 * AROW) + m] = __high2half(h01);
        vsh[(f0 + 2) * (2 * AROW) + m] = __low2half(h23);
        vsh[(f0 + 3) * (2 * AROW) + m] = __high2half(h23);
    }
    *(uint4*)&vsh[lane * (2 * AROW) + 24] = make_uint4(0, 0, 0, 0);
    __syncwarp();

    float cs[2][3][4];
#pragma unroll
    for (int mi = 0; mi < 2; mi++)
#pragma unroll
        for (int ni = 0; ni < 3; ni++)
#pragma unroll
            for (int j = 0; j < 4; j++) cs[mi][ni][j] = 0.f;

#pragma unroll
    for (int kb = 0; kb < 2; kb++) {
        uint32_t a[2][4];
#pragma unroll
        for (int mi = 0; mi < 2; mi++) {
            const int r = mi * 16 + gid;
            a[mi][0] = qs[(r)     * AROW + kb * 8 + tig];
            a[mi][1] = qs[(r + 8) * AROW + kb * 8 + tig];
            a[mi][2] = qs[(r)     * AROW + kb * 8 + tig + 4];
            a[mi][3] = qs[(r + 8) * AROW + kb * 8 + tig + 4];
        }
#pragma unroll
        for (int ni = 0; ni < 3; ni++) {
            uint32_t b[2];
            b[0] = ks[(ni * 8 + gid) * AROW + kb * 8 + tig];
            b[1] = ks[(ni * 8 + gid) * AROW + kb * 8 + tig + 4];
#pragma unroll
            for (int mi = 0; mi < 2; mi++) mma_f16(cs[mi][ni], a[mi], b);
        }
    }

    const float scale = 0.17677669529663687f;  // 1/sqrt(32)
    float p[2][3][4];
#pragma unroll
    for (int mi = 0; mi < 2; mi++) {
        float m0 = -1e30f, m1 = -1e30f;
#pragma unroll
        for (int ni = 0; ni < 3; ni++) {
            m0 = fmaxf(m0, fmaxf(cs[mi][ni][0], cs[mi][ni][1]));
            m1 = fmaxf(m1, fmaxf(cs[mi][ni][2], cs[mi][ni][3]));
        }
        m0 = fmaxf(m0, __shfl_xor_sync(0xffffffffu, m0, 1));
        m0 = fmaxf(m0, __shfl_xor_sync(0xffffffffu, m0, 2));
        m1 = fmaxf(m1, __shfl_xor_sync(0xffffffffu, m1, 1));
        m1 = fmaxf(m1, __shfl_xor_sync(0xffffffffu, m1, 2));

        float s0 = 0.f, s1 = 0.f;
#pragma unroll
        for (int ni = 0; ni < 3; ni++) {
            p[mi][ni][0] = __expf((cs[mi][ni][0] - m0) * scale);
            p[mi][ni][1] = __expf((cs[mi][ni][1] - m0) * scale);
            p[mi][ni][2] = __expf((cs[mi][ni][2] - m1) * scale);
            p[mi][ni][3] = __expf((cs[mi][ni][3] - m1) * scale);
            s0 += p[mi][ni][0] + p[mi][ni][1];
            s1 += p[mi][ni][2] + p[mi][ni][3];
        }
        s0 += __shfl_xor_sync(0xffffffffu, s0, 1);
        s0 += __shfl_xor_sync(0xffffffffu, s0, 2);
        s1 += __shfl_xor_sync(0xffffffffu, s1, 1);
        s1 += __shfl_xor_sync(0xffffffffu, s1, 2);
        const float i0 = __frcp_rn(s0), i1 = __frcp_rn(s1);
#pragma unroll
        for (int ni = 0; ni < 3; ni++) {
            p[mi][ni][0] *= i0; p[mi][ni][1] *= i0;
            p[mi][ni][2] *= i1; p[mi][ni][3] *= i1;
        }
    }

    float co[2][4][4];
#pragma unroll
    for (int mi = 0; mi < 2; mi++)
#pragma unroll
        for (int nj = 0; nj < 4; nj++)
#pragma unroll
            for (int j = 0; j < 4; j++) co[mi][nj][j] = 0.f;

#pragma unroll
    for (int mi = 0; mi < 2; mi++) {
        uint32_t ap0[4], ap1[4];
        ap0[0] = packh2(p[mi][0][0], p[mi][0][1]);
        ap0[1] = packh2(p[mi][0][2], p[mi][0][3]);
        ap0[2] = packh2(p[mi][1][0], p[mi][1][1]);
        ap0[3] = packh2(p[mi][1][2], p[mi][1][3]);
        ap1[0] = packh2(p[mi][2][0], p[mi][2][1]);
        ap1[1] = packh2(p[mi][2][2], p[mi][2][3]);
        ap1[2] = 0u; ap1[3] = 0u;
#pragma unroll
        for (int nj = 0; nj < 4; nj++) {
            uint32_t b0[2], b1[2];
            b0[0] = vs[(nj * 8 + gid) * AROW + tig];
            b0[1] = vs[(nj * 8 + gid) * AROW + tig + 4];
            b1[0] = vs[(nj * 8 + gid) * AROW + 8 + tig];
            b1[1] = vs[(nj * 8 + gid) * AROW + 8 + tig + 4];
            mma_f16(co[mi][nj], ap0, b0);
            mma_f16(co[mi][nj], ap1, b1);
        }
    }

#pragma unroll
    for (int mi = 0; mi < 2; mi++) {
        const int r0 = mi * 16 + gid;
#pragma unroll
        for (int nj = 0; nj < 4; nj++) {
            const int fcol = nj * 8 + 2 * tig;
            float2 v0;
            v0.x = co[mi][nj][0]; v0.y = co[mi][nj][1];
            *(float2*)&out[(size_t)tb * OUTW_ + (r0 * H_ + h) * F_ + fcol] = v0;
            if (mi == 0) {
                float2 v1;
                v1.x = co[mi][nj][2]; v1.y = co[mi][nj][3];
                *(float2*)&out[(size_t)tb * OUTW_ + ((r0 + 8) * H_ + h) * F_ + fcol] = v1;
            }
        }
    }
}

// ---------------------------------------------------------------------------
extern "C" void kernel_launch(void* const* d_in, const int* in_sizes, int n_in,
                              void* d_out, int out_size)
{
    const float* x  = (const float*)d_in[0];
    const float* Wk = (const float*)d_in[1];
    const float* bk = (const float*)d_in[2];
    const float* Wv = (const float*)d_in[3];
    const float* bv = (const float*)d_in[4];
    const float* Wq = (const float*)d_in[5];
    const float* bq = (const float*)d_in[6];
    float* out = (float*)d_out;

    cudaFuncSetAttribute(kv_mma_kernel,
                         cudaFuncAttributeMaxDynamicSharedMemorySize, KV_SMEM);
    cudaFuncSetAttribute(q_mma_kernel,
                         cudaFuncAttributeMaxDynamicSharedMemorySize, Q_SMEM);

    void* xh; void* wkh; void* wvh; void* wqh;
    cudaGetSymbolAddress(&xh,  g_xh);
    cudaGetSymbolAddress(&wkh, g_wkh);
    cudaGetSymbolAddress(&wvh, g_wvh);
    cudaGetSymbolAddress(&wqh, g_wqh);

    // Pre-pass: fp32 -> fp16 once.
    conv_h_kernel<<<8192, 256>>>((const float4*)x,  (uint2*)xh,  TB_ * ND_ / 4);
    conv_h_kernel<<<64,   256>>>((const float4*)Wk, (uint2*)wkh, HF_ * D_ / 4);
    conv_h_kernel<<<64,   256>>>((const float4*)Wv, (uint2*)wvh, HF_ * D_ / 4);
    conv_h_kernel<<<1536, 256>>>((const float4*)Wq, (uint2*)wqh, H_ * N_ * F_ * D_ / 4);

    dim3 g1(2, M1_ / 128);
    kv_mma_kernel<<<g1, 256, KV_SMEM>>>(bk, bv);

    dim3 g2(2, N_, TB_ / 128);
    q_mma_kernel<<<g2, 256, Q_SMEM>>>(bq);

    dim3 g3(TB_, 2);
    attn_kernel<<<g3, 128>>>(out);
}

// round 15
// speedup vs baseline: 1.9977x; 1.0455x over previous
#include <cuda_runtime.h>
#include <cuda_fp16.h>
#include <cstdint>
#include <math.h>

// Problem constants
#define T_    128
#define B_    64
#define TB_   8192      // T*B
#define N_    24        // joints
#define D_    256
#define H_    8
#define F_    32
#define HF_   256       // H*F
#define ND_   6144      // N*D
#define OUTW_ 6144      // N*H*F
#define M1_   196608    // TB*N rows for KV gemm

// fp16 scratch
__device__ __half g_q[TB_ * H_ * N_ * F_];
__device__ __half g_k[TB_ * H_ * N_ * F_];
__device__ __half g_v[TB_ * H_ * N_ * F_];
// fp16 copies of inputs (pre-converted once)
__device__ __half g_xh[TB_ * ND_];            // X   (100 MB)
__device__ __half g_wkh[HF_ * D_];
__device__ __half g_wvh[HF_ * D_];
__device__ __half g_wqh[H_ * N_ * F_ * D_];

// ---------------------------------------------------------------------------
// helpers
// ---------------------------------------------------------------------------
__device__ __forceinline__ uint32_t smem_u32(const void* p) {
    uint32_t a;
    asm("{ .reg .u64 t; cvta.to.shared.u64 t, %1; cvt.u32.u64 %0, t; }"
        : "=r"(a) : "l"(p));
    return a;
}
__device__ __forceinline__ void cp_async16(uint32_t dst, const void* src) {
    asm volatile("cp.async.cg.shared.global [%0], [%1], 16;"
                 :: "r"(dst), "l"(src) : "memory");
}
__device__ __forceinline__ void cp_commit() {
    asm volatile("cp.async.commit_group;" ::: "memory");
}
__device__ __forceinline__ void cp_wait1() {
    asm volatile("cp.async.wait_group 1;" ::: "memory");
}
__device__ __forceinline__ void cp_wait0() {
    asm volatile("cp.async.wait_group 0;" ::: "memory");
}
// fp16 m16n8k16, fp32 accumulate
__device__ __forceinline__ void mma_f16(float c[4], const uint32_t a[4],
                                        const uint32_t b[2]) {
    asm volatile(
        "mma.sync.aligned.m16n8k16.row.col.f32.f16.f16.f32 "
        "{%0,%1,%2,%3}, {%4,%5,%6,%7}, {%8,%9}, {%0,%1,%2,%3};"
        : "+f"(c[0]), "+f"(c[1]), "+f"(c[2]), "+f"(c[3])
        : "r"(a[0]), "r"(a[1]), "r"(a[2]), "r"(a[3]), "r"(b[0]), "r"(b[1]));
}
__device__ __forceinline__ uint32_t packh2(float x, float y) {
    __half2 h = __floats2half2_rn(x, y);
    return *reinterpret_cast<uint32_t*>(&h);
}
// warp-cooperative fragment load: 4 x (8x8 b16) matrices
#define LDMX4(d0, d1, d2, d3, addr)                                         \
    asm volatile("ldmatrix.sync.aligned.m8n8.x4.shared.b16 "                \
                 "{%0,%1,%2,%3}, [%4];"                                     \
                 : "=r"(d0), "=r"(d1), "=r"(d2), "=r"(d3) : "r"(addr))

// Smem geometry: K-chunk 64 halves = 32 words/row, padded to 36 words (144B).
// ldmatrix bank check: 8 consecutive rows at 36-word stride hit word offsets
// {0,4,...,28} mod 32 -> each 8-address phase covers all 32 banks once.
#define ROWW     36                         // words per row
#define ROWB     144                        // bytes per row
#define TILE_BYTES (128 * ROWW * 4)         // 18432

// KV fused: stage = A + Bk + Bv
#define KV_STAGE   (3 * TILE_BYTES)         // 55296
#define KV_NSTG    3
#define KV_SMEM    (KV_NSTG * KV_STAGE + 1024)  // 166912 -> 1 CTA/SM

// Q: stage = A + B
#define Q_STAGE    (2 * TILE_BYTES)         // 36864
#define Q_NSTG     3
#define Q_SMEM     (Q_NSTG * Q_STAGE + 1024)    // 111616 -> 2 CTA/SM

// ---------------------------------------------------------------------------
// Pre-pass: fp32 -> fp16, vectorized.
// ---------------------------------------------------------------------------
__global__ void conv_h_kernel(const float4* __restrict__ src,
                              uint2* __restrict__ dst, int n4)
{
    for (int i = blockIdx.x * blockDim.x + threadIdx.x; i < n4;
         i += gridDim.x * blockDim.x) {
        float4 v = src[i];
        __half2 a = __floats2half2_rn(v.x, v.y);
        __half2 b = __floats2half2_rn(v.z, v.w);
        uint2 u;
        u.x = *reinterpret_cast<const uint32_t*>(&a);
        u.y = *reinterpret_cast<const uint32_t*>(&b);
        dst[i] = u;
    }
}

// Per-lane ldmatrix source offsets (bytes), relative to tile base:
//  A (x4 = a0,a1,a2,a3): m0 rows0-7 k0 | m1 rows8-15 k0 | m2 rows0-7 k8 | m3 rows8-15 k8
//  B (x4 = b0(ni),b1(ni),b0(ni+1),b1(ni+1)):
//     m0 rows0-7 k0 | m1 rows0-7 k8 | m2 rows8-15 k0 | m3 rows8-15 k8
#define A_LANE_OFF(mBase, lane) \
    ((uint32_t)(((mBase) + (((lane) >> 3) & 1) * 8 + ((lane) & 7)) * ROWB + (((lane) >> 4) & 1) * 16))
#define B_LANE_OFF(nBase, lane) \
    ((uint32_t)(((nBase) + (((lane) >> 4) & 1) * 8 + ((lane) & 7)) * ROWB + (((lane) >> 3) & 1) * 16))

// ---------------------------------------------------------------------------
// Kernel 1: fused K+V projection. grid (2, 1536): x=N-tile, y=M-tile.
// ---------------------------------------------------------------------------
__global__ void __launch_bounds__(256, 1)
kv_mma_kernel(const float* __restrict__ bk, const float* __restrict__ bv)
{
    extern __shared__ char smem[];
    const int tid  = threadIdx.x;
    const int w    = tid >> 5, lane = tid & 31;
    const int gid  = lane >> 2, tig = lane & 3;
    const int mWarp = (w & 1) * 64;
    const int nWarp = (w >> 1) * 32;
    const int colBase = blockIdx.x * 128;
    const int rowBase = blockIdx.y * 128;
    const uint32_t sb = smem_u32(smem);

    const uint32_t aLane = A_LANE_OFF(mWarp, lane);
    const uint32_t bLane = B_LANE_OFF(nWarp, lane);

    float* sbK = (float*)(smem + KV_NSTG * KV_STAGE);
    float* sbV = sbK + 128;
    if (tid < 128) { sbK[tid] = bk[colBase + tid]; sbV[tid] = bv[colBase + tid]; }

    float cK[4][4][4], cV[4][4][4];
#pragma unroll
    for (int mi = 0; mi < 4; mi++)
#pragma unroll
        for (int ni = 0; ni < 4; ni++)
#pragma unroll
            for (int j = 0; j < 4; j++) { cK[mi][ni][j] = 0.f; cV[mi][ni][j] = 0.f; }

    auto load_stage = [&](int ch) {
        const int s = ch % KV_NSTG;
        const int k0 = ch * 64;                 // halves
        const uint32_t aBase  = sb + s * KV_STAGE;
        const uint32_t bkBase = aBase + TILE_BYTES;
        const uint32_t bvBase = aBase + 2 * TILE_BYTES;
#pragma unroll
        for (int j = 0; j < 4; j++) {
            const int e = tid + 256 * j;
            const int r = e >> 3, cc = e & 7;   // 8 x 16B per 128B row
            const uint32_t soff = (uint32_t)(r * ROWB + cc * 16);
            cp_async16(aBase + soff,
                       g_xh + (size_t)(rowBase + r) * D_ + k0 + cc * 8);
            cp_async16(bkBase + soff,
                       g_wkh + (size_t)(colBase + r) * D_ + k0 + cc * 8);
            cp_async16(bvBase + soff,
                       g_wvh + (size_t)(colBase + r) * D_ + k0 + cc * 8);
        }
    };

    load_stage(0); cp_commit();
    load_stage(1); cp_commit();

    for (int ch = 0; ch < 4; ch++) {
        if (ch < 3) cp_wait1(); else cp_wait0();
        __syncthreads();
        if (ch + 2 < 4) { load_stage(ch + 2); cp_commit(); }
        const uint32_t aBase  = sb + (ch % KV_NSTG) * KV_STAGE;
        const uint32_t bkBase = aBase + TILE_BYTES;
        const uint32_t bvBase = aBase + 2 * TILE_BYTES;
#pragma unroll
        for (int ks = 0; ks < 4; ks++) {
            const uint32_t kOff = (uint32_t)(ks * 32);      // 8 words = 32 B
            uint32_t af[4][4];
#pragma unroll
            for (int mi = 0; mi < 4; mi++)
                LDMX4(af[mi][0], af[mi][1], af[mi][2], af[mi][3],
                      aBase + aLane + (uint32_t)(mi * 16 * ROWB) + kOff);
            uint32_t bK[4][2], bV[4][2];
#pragma unroll
            for (int np = 0; np < 2; np++) {                // ni pairs (0,1),(2,3)
                const uint32_t bo = bLane + (uint32_t)(np * 16 * ROWB) + kOff;
                LDMX4(bK[2 * np][0], bK[2 * np][1], bK[2 * np + 1][0], bK[2 * np + 1][1],
                      bkBase + bo);
                LDMX4(bV[2 * np][0], bV[2 * np][1], bV[2 * np + 1][0], bV[2 * np + 1][1],
                      bvBase + bo);
            }
#pragma unroll
            for (int ni = 0; ni < 4; ni++)
#pragma unroll
                for (int mi = 0; mi < 4; mi++) {
                    mma_f16(cK[mi][ni], af[mi], bK[ni]);
                    mma_f16(cV[mi][ni], af[mi], bV[ni]);
                }
        }
    }

#pragma unroll
    for (int mi = 0; mi < 4; mi++) {
        const int r0 = rowBase + mWarp + mi * 16 + gid;
#pragma unroll
        for (int rr = 0; rr < 2; rr++) {
            const int m = r0 + rr * 8;
            const int tb = m / N_, n = m - tb * N_;
#pragma unroll
            for (int ni = 0; ni < 4; ni++) {
                const int oc = nWarp + ni * 8 + tig * 2;
                const int o = colBase + oc;
                const int h = o >> 5, f = o & 31;
                const size_t idx = (((size_t)tb * H_ + h) * N_ + n) * F_ + f;
                __half2 vk = __floats2half2_rn(cK[mi][ni][2 * rr + 0] + sbK[oc],
                                               cK[mi][ni][2 * rr + 1] + sbK[oc + 1]);
                __half2 vv = __floats2half2_rn(cV[mi][ni][2 * rr + 0] + sbV[oc],
                                               cV[mi][ni][2 * rr + 1] + sbV[oc + 1]);
                *(__half2*)&g_k[idx] = vk;
                *(__half2*)&g_v[idx] = vv;
            }
        }
    }
}

// ---------------------------------------------------------------------------
// Kernel 2: Q projection. grid (2, 24, 64): x=N-tile, y=joint, z=tb-tile.
// ---------------------------------------------------------------------------
__global__ void __launch_bounds__(256, 2)
q_mma_kernel(const float* __restrict__ bq)
{
    extern __shared__ char smem[];
    const int nJ = blockIdx.y;

    const int tid  = threadIdx.x;
    const int w    = tid >> 5, lane = tid & 31;
    const int gid  = lane >> 2, tig = lane & 3;
    const int mWarp = (w & 1) * 64;
    const int nWarp = (w >> 1) * 32;
    const int colBase = blockIdx.x * 128;
    const int rowBase = blockIdx.z * 128;
    const uint32_t sb = smem_u32(smem);

    const uint32_t aLane = A_LANE_OFF(mWarp, lane);
    const uint32_t bLane = B_LANE_OFF(nWarp, lane);

    float* sbias = (float*)(smem + Q_NSTG * Q_STAGE);
    if (tid < 128) {
        const int o = colBase + tid;
        const int h = o >> 5, f = o & 31;
        sbias[tid] = bq[(h * N_ + nJ) * F_ + f];
    }

    float c[4][4][4];
#pragma unroll
    for (int mi = 0; mi < 4; mi++)
#pragma unroll
        for (int ni = 0; ni < 4; ni++)
#pragma unroll
            for (int j = 0; j < 4; j++) c[mi][ni][j] = 0.f;

    auto load_stage = [&](int ch) {
        const int s = ch % Q_NSTG;
        const int k0 = ch * 64;
        const uint32_t aBase = sb + s * Q_STAGE;
        const uint32_t bBase = aBase + TILE_BYTES;
#pragma unroll
        for (int j = 0; j < 4; j++) {
            const int e = tid + 256 * j;
            const int r = e >> 3, cc = e & 7;
            const uint32_t soff = (uint32_t)(r * ROWB + cc * 16);
            cp_async16(aBase + soff,
                       g_xh + (size_t)(rowBase + r) * ND_ + nJ * D_ + k0 + cc * 8);
            const int o = colBase + r;
            const int h = o >> 5, f = o & 31;
            cp_async16(bBase + soff,
                       g_wqh + ((size_t)(h * N_ + nJ) * F_ + f) * D_ + k0 + cc * 8);
        }
    };

    load_stage(0); cp_commit();
    load_stage(1); cp_commit();

    for (int ch = 0; ch < 4; ch++) {
        if (ch < 3) cp_wait1(); else cp_wait0();
        __syncthreads();
        if (ch + 2 < 4) { load_stage(ch + 2); cp_commit(); }
        const uint32_t aBase = sb + (ch % Q_NSTG) * Q_STAGE;
        const uint32_t bBase = aBase + TILE_BYTES;
#pragma unroll
        for (int ks = 0; ks < 4; ks++) {
            const uint32_t kOff = (uint32_t)(ks * 32);
            uint32_t af[4][4];
#pragma unroll
            for (int mi = 0; mi < 4; mi++)
                LDMX4(af[mi][0], af[mi][1], af[mi][2], af[mi][3],
                      aBase + aLane + (uint32_t)(mi * 16 * ROWB) + kOff);
            uint32_t bf[4][2];
#pragma unroll
            for (int np = 0; np < 2; np++) {
                LDMX4(bf[2 * np][0], bf[2 * np][1], bf[2 * np + 1][0], bf[2 * np + 1][1],
                      bBase + bLane + (uint32_t)(np * 16 * ROWB) + kOff);
            }
#pragma unroll
            for (int mi = 0; mi < 4; mi++)
#pragma unroll
                for (int ni = 0; ni < 4; ni++)
                    mma_f16(c[mi][ni], af[mi], bf[ni]);
        }
    }

#pragma unroll
    for (int mi = 0; mi < 4; mi++) {
        const int r0 = rowBase + mWarp + mi * 16 + gid;
#pragma unroll
        for (int rr = 0; rr < 2; rr++) {
            const int tb = r0 + rr * 8;
#pragma unroll
            for (int ni = 0; ni < 4; ni++) {
                const int oc = nWarp + ni * 8 + tig * 2;
                const int o = colBase + oc;
                const int h = o >> 5, f = o & 31;
                __half2 v = __floats2half2_rn(c[mi][ni][2 * rr + 0] + sbias[oc],
                                              c[mi][ni][2 * rr + 1] + sbias[oc + 1]);
                *(__half2*)&g_q[(((size_t)tb * H_ + h) * N_ + nJ) * F_ + f] = v;
            }
        }
    }
}

// ---------------------------------------------------------------------------
// Kernel 3: tensor-core attention (unchanged from R11, validated).
// ---------------------------------------------------------------------------
#define AROW 20   // words per smem row (conflict-free)

__global__ __launch_bounds__(128)
void attn_kernel(float* __restrict__ out)
{
    __shared__ uint32_t sm[4][3][32 * AROW];

    const int tb   = blockIdx.x;
    const int w    = threadIdx.x >> 5;
    const int lane = threadIdx.x & 31;
    const int gid  = lane >> 2, tig = lane & 3;
    const int h    = blockIdx.y * 4 + w;

    uint32_t* qs = sm[w][0];
    uint32_t* ks = sm[w][1];
    uint32_t* vs = sm[w][2];

    const size_t base = ((size_t)(tb * H_ + h)) * N_ * F_;
    const uint2* qg = (const uint2*)(g_q + base);
    const uint2* kg = (const uint2*)(g_k + base);
    const uint2* vg = (const uint2*)(g_v + base);

    for (int i = lane; i < 24 * 8; i += 32) {
        const int r = i >> 3, cc = i & 7;
        *(uint2*)&qs[r * AROW + cc * 2] = qg[i];
        *(uint2*)&ks[r * AROW + cc * 2] = kg[i];
    }
    __half* vsh = (__half*)vs;
    for (int i = lane; i < 24 * 8; i += 32) {
        const int m = i >> 3, cc = i & 7;
        uint2 u = vg[i];
        __half2 h01 = *(__half2*)&u.x, h23 = *(__half2*)&u.y;
        const int f0 = cc * 4;
        vsh[(f0 + 0) * (2 * AROW) + m] = __low2half(h01);
        vsh[(f0 + 1) * (2 * AROW) + m] = __high2half(h01);
        vsh[(f0 + 2) * (2 * AROW) + m] = __low2half(h23);
        vsh[(f0 + 3) * (2 * AROW) + m] = __high2half(h23);
    }
    *(uint4*)&vsh[lane * (2 * AROW) + 24] = make_uint4(0, 0, 0, 0);
    __syncwarp();

    float cs[2][3][4];
#pragma unroll
    for (int mi = 0; mi < 2; mi++)
#pragma unroll
        for (int ni = 0; ni < 3; ni++)
#pragma unroll
            for (int j = 0; j < 4; j++) cs[mi][ni][j] = 0.f;

#pragma unroll
    for (int kb = 0; kb < 2; kb++) {
        uint32_t a[2][4];
#pragma unroll
        for (int mi = 0; mi < 2; mi++) {
            const int r = mi * 16 + gid;
            a[mi][0] = qs[(r)     * AROW + kb * 8 + tig];
            a[mi][1] = qs[(r + 8) * AROW + kb * 8 + tig];
            a[mi][2] = qs[(r)     * AROW + kb * 8 + tig + 4];
            a[mi][3] = qs[(r + 8) * AROW + kb * 8 + tig + 4];
        }
#pragma unroll
        for (int ni = 0; ni < 3; ni++) {
            uint32_t b[2];
            b[0] = ks[(ni * 8 + gid) * AROW + kb * 8 + tig];
            b[1] = ks[(ni * 8 + gid) * AROW + kb * 8 + tig + 4];
#pragma unroll
            for (int mi = 0; mi < 2; mi++) mma_f16(cs[mi][ni], a[mi], b);
        }
    }

    const float scale = 0.17677669529663687f;  // 1/sqrt(32)
    float p[2][3][4];
#pragma unroll
    for (int mi = 0; mi < 2; mi++) {
        float m0 = -1e30f, m1 = -1e30f;
#pragma unroll
        for (int ni = 0; ni < 3; ni++) {
            m0 = fmaxf(m0, fmaxf(cs[mi][ni][0], cs[mi][ni][1]));
            m1 = fmaxf(m1, fmaxf(cs[mi][ni][2], cs[mi][ni][3]));
        }
        m0 = fmaxf(m0, __shfl_xor_sync(0xffffffffu, m0, 1));
        m0 = fmaxf(m0, __shfl_xor_sync(0xffffffffu, m0, 2));
        m1 = fmaxf(m1, __shfl_xor_sync(0xffffffffu, m1, 1));
        m1 = fmaxf(m1, __shfl_xor_sync(0xffffffffu, m1, 2));

        float s0 = 0.f, s1 = 0.f;
#pragma unroll
        for (int ni = 0; ni < 3; ni++) {
            p[mi][ni][0] = __expf((cs[mi][ni][0] - m0) * scale);
            p[mi][ni][1] = __expf((cs[mi][ni][1] - m0) * scale);
            p[mi][ni][2] = __expf((cs[mi][ni][2] - m1) * scale);
            p[mi][ni][3] = __expf((cs[mi][ni][3] - m1) * scale);
            s0 += p[mi][ni][0] + p[mi][ni][1];
            s1 += p[mi][ni][2] + p[mi][ni][3];
        }
        s0 += __shfl_xor_sync(0xffffffffu, s0, 1);
        s0 += __shfl_xor_sync(0xffffffffu, s0, 2);
        s1 += __shfl_xor_sync(0xffffffffu, s1, 1);
        s1 += __shfl_xor_sync(0xffffffffu, s1, 2);
        const float i0 = __frcp_rn(s0), i1 = __frcp_rn(s1);
#pragma unroll
        for (int ni = 0; ni < 3; ni++) {
            p[mi][ni][0] *= i0; p[mi][ni][1] *= i0;
            p[mi][ni][2] *= i1; p[mi][ni][3] *= i1;
        }
    }

    float co[2][4][4];
#pragma unroll
    for (int mi = 0; mi < 2; mi++)
#pragma unroll
        for (int nj = 0; nj < 4; nj++)
#pragma unroll
            for (int j = 0; j < 4; j++) co[mi][nj][j] = 0.f;

#pragma unroll
    for (int mi = 0; mi < 2; mi++) {
        uint32_t ap0[4], ap1[4];
        ap0[0] = packh2(p[mi][0][0], p[mi][0][1]);
        ap0[1] = packh2(p[mi][0][2], p[mi][0][3]);
        ap0[2] = packh2(p[mi][1][0], p[mi][1][1]);
        ap0[3] = packh2(p[mi][1][2], p[mi][1][3]);
        ap1[0] = packh2(p[mi][2][0], p[mi][2][1]);
        ap1[1] = packh2(p[mi][2][2], p[mi][2][3]);
        ap1[2] = 0u; ap1[3] = 0u;
#pragma unroll
        for (int nj = 0; nj < 4; nj++) {
            uint32_t b0[2], b1[2];
            b0[0] = vs[(nj * 8 + gid) * AROW + tig];
            b0[1] = vs[(nj * 8 + gid) * AROW + tig + 4];
            b1[0] = vs[(nj * 8 + gid) * AROW + 8 + tig];
            b1[1] = vs[(nj * 8 + gid) * AROW + 8 + tig + 4];
            mma_f16(co[mi][nj], ap0, b0);
            mma_f16(co[mi][nj], ap1, b1);
        }
    }

#pragma unroll
    for (int mi = 0; mi < 2; mi++) {
        const int r0 = mi * 16 + gid;
#pragma unroll
        for (int nj = 0; nj < 4; nj++) {
            const int fcol = nj * 8 + 2 * tig;
            float2 v0;
            v0.x = co[mi][nj][0]; v0.y = co[mi][nj][1];
            *(float2*)&out[(size_t)tb * OUTW_ + (r0 * H_ + h) * F_ + fcol] = v0;
            if (mi == 0) {
                float2 v1;
                v1.x = co[mi][nj][2]; v1.y = co[mi][nj][3];
                *(float2*)&out[(size_t)tb * OUTW_ + ((r0 + 8) * H_ + h) * F_ + fcol] = v1;
            }
        }
    }
}

// ---------------------------------------------------------------------------
extern "C" void kernel_launch(void* const* d_in, const int* in_sizes, int n_in,
                              void* d_out, int out_size)
{
    const float* x  = (const float*)d_in[0];
    const float* Wk = (const float*)d_in[1];
    const float* bk = (const float*)d_in[2];
    const float* Wv = (const float*)d_in[3];
    const float* bv = (const float*)d_in[4];
    const float* Wq = (const float*)d_in[5];
    const float* bq = (const float*)d_in[6];
    float* out = (float*)d_out;

    cudaFuncSetAttribute(kv_mma_kernel,
                         cudaFuncAttributeMaxDynamicSharedMemorySize, KV_SMEM);
    cudaFuncSetAttribute(q_mma_kernel,
                         cudaFuncAttributeMaxDynamicSharedMemorySize, Q_SMEM);

    void* xh; void* wkh; void* wvh; void* wqh;
    cudaGetSymbolAddress(&xh,  g_xh);
    cudaGetSymbolAddress(&wkh, g_wkh);
    cudaGetSymbolAddress(&wvh, g_wvh);
    cudaGetSymbolAddress(&wqh, g_wqh);

    // Pre-pass: fp32 -> fp16 once.
    conv_h_kernel<<<8192, 256>>>((const float4*)x,  (uint2*)xh,  TB_ * ND_ / 4);
    conv_h_kernel<<<64,   256>>>((const float4*)Wk, (uint2*)wkh, HF_ * D_ / 4);
    conv_h_kernel<<<64,   256>>>((const float4*)Wv, (uint2*)wvh, HF_ * D_ / 4);
    conv_h_kernel<<<1536, 256>>>((const float4*)Wq, (uint2*)wqh, H_ * N_ * F_ * D_ / 4);

    dim3 g1(2, M1_ / 128);
    kv_mma_kernel<<<g1, 256, KV_SMEM>>>(bk, bv);

    dim3 g2(2, N_, TB_ / 128);
    q_mma_kernel<<<g2, 256, Q_SMEM>>>(bq);

    dim3 g3(TB_, 2);
    attn_kernel<<<g3, 128>>>(out);
}

// round 16
// speedup vs baseline: 1.9997x; 1.0010x over previous
#include <cuda_runtime.h>
#include <cuda_fp16.h>
#include <cstdint>
#include <math.h>

// Problem constants
#define T_    128
#define B_    64
#define TB_   8192      // T*B
#define N_    24        // joints
#define D_    256
#define H_    8
#define F_    32
#define HF_   256       // H*F
#define ND_   6144      // N*D
#define OUTW_ 6144      // N*H*F
#define M1_   196608    // TB*N rows for KV gemm

// fp16 scratch
__device__ __half g_q[TB_ * H_ * N_ * F_];
__device__ __half g_k[TB_ * H_ * N_ * F_];
__device__ __half g_v[TB_ * H_ * N_ * F_];
// fp16 copies of inputs (pre-converted once)
__device__ __half g_xh[TB_ * ND_];            // X   (100 MB)
__device__ __half g_wkh[HF_ * D_];
__device__ __half g_wvh[HF_ * D_];
__device__ __half g_wqh[H_ * N_ * F_ * D_];

// ---------------------------------------------------------------------------
// helpers
// ---------------------------------------------------------------------------
__device__ __forceinline__ uint32_t smem_u32(const void* p) {
    uint32_t a;
    asm("{ .reg .u64 t; cvta.to.shared.u64 t, %1; cvt.u32.u64 %0, t; }"
        : "=r"(a) : "l"(p));
    return a;
}
__device__ __forceinline__ void cp_async16(uint32_t dst, const void* src) {
    asm volatile("cp.async.cg.shared.global [%0], [%1], 16;"
                 :: "r"(dst), "l"(src) : "memory");
}
__device__ __forceinline__ void cp_commit() {
    asm volatile("cp.async.commit_group;" ::: "memory");
}
__device__ __forceinline__ void cp_wait1() {
    asm volatile("cp.async.wait_group 1;" ::: "memory");
}
__device__ __forceinline__ void cp_wait0() {
    asm volatile("cp.async.wait_group 0;" ::: "memory");
}
// fp16 m16n8k16, fp32 accumulate
__device__ __forceinline__ void mma_f16(float c[4], const uint32_t a[4],
                                        const uint32_t b[2]) {
    asm volatile(
        "mma.sync.aligned.m16n8k16.row.col.f32.f16.f16.f32 "
        "{%0,%1,%2,%3}, {%4,%5,%6,%7}, {%8,%9}, {%0,%1,%2,%3};"
        : "+f"(c[0]), "+f"(c[1]), "+f"(c[2]), "+f"(c[3])
        : "r"(a[0]), "r"(a[1]), "r"(a[2]), "r"(a[3]), "r"(b[0]), "r"(b[1]));
}
__device__ __forceinline__ uint32_t packh2(float x, float y) {
    __half2 h = __floats2half2_rn(x, y);
    return *reinterpret_cast<uint32_t*>(&h);
}
// warp-cooperative fragment load: 4 x (8x8 b16) matrices
#define LDMX4(d0, d1, d2, d3, addr)                                         \
    asm volatile("ldmatrix.sync.aligned.m8n8.x4.shared.b16 "                \
                 "{%0,%1,%2,%3}, [%4];"                                     \
                 : "=r"(d0), "=r"(d1), "=r"(d2), "=r"(d3) : "r"(addr))

// Smem geometry: K-chunk 64 halves = 32 words/row, padded to 36 words (144B).
// ldmatrix bank check: 8 consecutive rows at 36-word stride hit word offsets
// {0,4,...,28} mod 32 -> each 8-address phase covers all 32 banks once.
#define ROWW     36                         // words per row
#define ROWB     144                        // bytes per row
#define TILE_BYTES (128 * ROWW * 4)         // 18432

// KV fused: stage = A + Bk + Bv
#define KV_STAGE   (3 * TILE_BYTES)         // 55296
#define KV_NSTG    3
#define KV_SMEM    (KV_NSTG * KV_STAGE + 1024)  // 166912 -> 1 CTA/SM

// Q: stage = A + B
#define Q_STAGE    (2 * TILE_BYTES)         // 36864
#define Q_NSTG     3
#define Q_SMEM     (Q_NSTG * Q_STAGE + 1024)    // 111616 -> 2 CTA/SM

// ---------------------------------------------------------------------------
// Pre-pass: fp32 -> fp16, vectorized.
// ---------------------------------------------------------------------------
__global__ void conv_h_kernel(const float4* __restrict__ src,
                              uint2* __restrict__ dst, int n4)
{
    for (int i = blockIdx.x * blockDim.x + threadIdx.x; i < n4;
         i += gridDim.x * blockDim.x) {
        float4 v = src[i];
        __half2 a = __floats2half2_rn(v.x, v.y);
        __half2 b = __floats2half2_rn(v.z, v.w);
        uint2 u;
        u.x = *reinterpret_cast<const uint32_t*>(&a);
        u.y = *reinterpret_cast<const uint32_t*>(&b);
        dst[i] = u;
    }
}

// Per-lane ldmatrix source offsets (bytes), relative to tile base:
//  A (x4 = a0,a1,a2,a3): m0 rows0-7 k0 | m1 rows8-15 k0 | m2 rows0-7 k8 | m3 rows8-15 k8
//  B (x4 = b0(ni),b1(ni),b0(ni+1),b1(ni+1)):
//     m0 rows0-7 k0 | m1 rows0-7 k8 | m2 rows8-15 k0 | m3 rows8-15 k8
#define A_LANE_OFF(mBase, lane) \
    ((uint32_t)(((mBase) + (((lane) >> 3) & 1) * 8 + ((lane) & 7)) * ROWB + (((lane) >> 4) & 1) * 16))
#define B_LANE_OFF(nBase, lane) \
    ((uint32_t)(((nBase) + (((lane) >> 4) & 1) * 8 + ((lane) & 7)) * ROWB + (((lane) >> 3) & 1) * 16))

// ---------------------------------------------------------------------------
// Kernel 1: fused K+V projection. grid (2, 1536): x=N-tile, y=M-tile.
// ---------------------------------------------------------------------------
__global__ void __launch_bounds__(256, 1)
kv_mma_kernel(const float* __restrict__ bk, const float* __restrict__ bv)
{
    extern __shared__ char smem[];
    const int tid  = threadIdx.x;
    const int w    = tid >> 5, lane = tid & 31;
    const int gid  = lane >> 2, tig = lane & 3;
    const int mWarp = (w & 1) * 64;
    const int nWarp = (w >> 1) * 32;
    const int colBase = blockIdx.x * 128;
    const int rowBase = blockIdx.y * 128;
    const uint32_t sb = smem_u32(smem);

    const uint32_t aLane = A_LANE_OFF(mWarp, lane);
    const uint32_t bLane = B_LANE_OFF(nWarp, lane);

    float* sbK = (float*)(smem + KV_NSTG * KV_STAGE);
    float* sbV = sbK + 128;
    if (tid < 128) { sbK[tid] = bk[colBase + tid]; sbV[tid] = bv[colBase + tid]; }

    float cK[4][4][4], cV[4][4][4];
#pragma unroll
    for (int mi = 0; mi < 4; mi++)
#pragma unroll
        for (int ni = 0; ni < 4; ni++)
#pragma unroll
            for (int j = 0; j < 4; j++) { cK[mi][ni][j] = 0.f; cV[mi][ni][j] = 0.f; }

    auto load_stage = [&](int ch) {
        const int s = ch % KV_NSTG;
        const int k0 = ch * 64;                 // halves
        const uint32_t aBase  = sb + s * KV_STAGE;
        const uint32_t bkBase = aBase + TILE_BYTES;
        const uint32_t bvBase = aBase + 2 * TILE_BYTES;
#pragma unroll
        for (int j = 0; j < 4; j++) {
            const int e = tid + 256 * j;
            const int r = e >> 3, cc = e & 7;   // 8 x 16B per 128B row
            const uint32_t soff = (uint32_t)(r * ROWB + cc * 16);
            cp_async16(aBase + soff,
                       g_xh + (size_t)(rowBase + r) * D_ + k0 + cc * 8);
            cp_async16(bkBase + soff,
                       g_wkh + (size_t)(colBase + r) * D_ + k0 + cc * 8);
            cp_async16(bvBase + soff,
                       g_wvh + (size_t)(colBase + r) * D_ + k0 + cc * 8);
        }
    };

    load_stage(0); cp_commit();
    load_stage(1); cp_commit();

    for (int ch = 0; ch < 4; ch++) {
        if (ch < 3) cp_wait1(); else cp_wait0();
        __syncthreads();
        if (ch + 2 < 4) { load_stage(ch + 2); cp_commit(); }
        const uint32_t aBase  = sb + (ch % KV_NSTG) * KV_STAGE;
        const uint32_t bkBase = aBase + TILE_BYTES;
        const uint32_t bvBase = aBase + 2 * TILE_BYTES;
#pragma unroll
        for (int ks = 0; ks < 4; ks++) {
            const uint32_t kOff = (uint32_t)(ks * 32);      // 8 words = 32 B
            uint32_t af[4][4];
#pragma unroll
            for (int mi = 0; mi < 4; mi++)
                LDMX4(af[mi][0], af[mi][1], af[mi][2], af[mi][3],
                      aBase + aLane + (uint32_t)(mi * 16 * ROWB) + kOff);
            uint32_t bK[4][2], bV[4][2];
#pragma unroll
            for (int np = 0; np < 2; np++) {                // ni pairs (0,1),(2,3)
                const uint32_t bo = bLane + (uint32_t)(np * 16 * ROWB) + kOff;
                LDMX4(bK[2 * np][0], bK[2 * np][1], bK[2 * np + 1][0], bK[2 * np + 1][1],
                      bkBase + bo);
                LDMX4(bV[2 * np][0], bV[2 * np][1], bV[2 * np + 1][0], bV[2 * np + 1][1],
                      bvBase + bo);
            }
#pragma unroll
            for (int ni = 0; ni < 4; ni++)
#pragma unroll
                for (int mi = 0; mi < 4; mi++) {
                    mma_f16(cK[mi][ni], af[mi], bK[ni]);
                    mma_f16(cV[mi][ni], af[mi], bV[ni]);
                }
        }
    }

#pragma unroll
    for (int mi = 0; mi < 4; mi++) {
        const int r0 = rowBase + mWarp + mi * 16 + gid;
#pragma unroll
        for (int rr = 0; rr < 2; rr++) {
            const int m = r0 + rr * 8;
            const int tb = m / N_, n = m - tb * N_;
#pragma unroll
            for (int ni = 0; ni < 4; ni++) {
                const int oc = nWarp + ni * 8 + tig * 2;
                const int o = colBase + oc;
                const int h = o >> 5, f = o & 31;
                const size_t idx = (((size_t)tb * H_ + h) * N_ + n) * F_ + f;
                __half2 vk = __floats2half2_rn(cK[mi][ni][2 * rr + 0] + sbK[oc],
                                               cK[mi][ni][2 * rr + 1] + sbK[oc + 1]);
                __half2 vv = __floats2half2_rn(cV[mi][ni][2 * rr + 0] + sbV[oc],
                                               cV[mi][ni][2 * rr + 1] + sbV[oc + 1]);
                *(__half2*)&g_k[idx] = vk;
                *(__half2*)&g_v[idx] = vv;
            }
        }
    }
}

// ---------------------------------------------------------------------------
// Kernel 2: Q projection. grid (2, 24, 64): x=N-tile, y=joint, z=tb-tile.
// ---------------------------------------------------------------------------
__global__ void __launch_bounds__(256, 2)
q_mma_kernel(const float* __restrict__ bq)
{
    extern __shared__ char smem[];
    const int nJ = blockIdx.y;

    const int tid  = threadIdx.x;
    const int w    = tid >> 5, lane = tid & 31;
    const int gid  = lane >> 2, tig = lane & 3;
    const int mWarp = (w & 1) * 64;
    const int nWarp = (w >> 1) * 32;
    const int colBase = blockIdx.x * 128;
    const int rowBase = blockIdx.z * 128;
    const uint32_t sb = smem_u32(smem);

    const uint32_t aLane = A_LANE_OFF(mWarp, lane);
    const uint32_t bLane = B_LANE_OFF(nWarp, lane);

    float* sbias = (float*)(smem + Q_NSTG * Q_STAGE);
    if (tid < 128) {
        const int o = colBase + tid;
        const int h = o >> 5, f = o & 31;
        sbias[tid] = bq[(h * N_ + nJ) * F_ + f];
    }

    float c[4][4][4];
#pragma unroll
    for (int mi = 0; mi < 4; mi++)
#pragma unroll
        for (int ni = 0; ni < 4; ni++)
#pragma unroll
            for (int j = 0; j < 4; j++) c[mi][ni][j] = 0.f;

    auto load_stage = [&](int ch) {
        const int s = ch % Q_NSTG;
        const int k0 = ch * 64;
        const uint32_t aBase = sb + s * Q_STAGE;
        const uint32_t bBase = aBase + TILE_BYTES;
#pragma unroll
        for (int j = 0; j < 4; j++) {
            const int e = tid + 256 * j;
            const int r = e >> 3, cc = e & 7;
            const uint32_t soff = (uint32_t)(r * ROWB + cc * 16);
            cp_async16(aBase + soff,
                       g_xh + (size_t)(rowBase + r) * ND_ + nJ * D_ + k0 + cc * 8);
            const int o = colBase + r;
            const int h = o >> 5, f = o & 31;
            cp_async16(bBase + soff,
                       g_wqh + ((size_t)(h * N_ + nJ) * F_ + f) * D_ + k0 + cc * 8);
        }
    };

    load_stage(0); cp_commit();
    load_stage(1); cp_commit();

    for (int ch = 0; ch < 4; ch++) {
        if (ch < 3) cp_wait1(); else cp_wait0();
        __syncthreads();
        if (ch + 2 < 4) { load_stage(ch + 2); cp_commit(); }
        const uint32_t aBase = sb + (ch % Q_NSTG) * Q_STAGE;
        const uint32_t bBase = aBase + TILE_BYTES;
#pragma unroll
        for (int ks = 0; ks < 4; ks++) {
            const uint32_t kOff = (uint32_t)(ks * 32);
            uint32_t af[4][4];
#pragma unroll
            for (int mi = 0; mi < 4; mi++)
                LDMX4(af[mi][0], af[mi][1], af[mi][2], af[mi][3],
                      aBase + aLane + (uint32_t)(mi * 16 * ROWB) + kOff);
            uint32_t bf[4][2];
#pragma unroll
            for (int np = 0; np < 2; np++) {
                LDMX4(bf[2 * np][0], bf[2 * np][1], bf[2 * np + 1][0], bf[2 * np + 1][1],
                      bBase + bLane + (uint32_t)(np * 16 * ROWB) + kOff);
            }
#pragma unroll
            for (int mi = 0; mi < 4; mi++)
#pragma unroll
                for (int ni = 0; ni < 4; ni++)
                    mma_f16(c[mi][ni], af[mi], bf[ni]);
        }
    }

#pragma unroll
    for (int mi = 0; mi < 4; mi++) {
        const int r0 = rowBase + mWarp + mi * 16 + gid;
#pragma unroll
        for (int rr = 0; rr < 2; rr++) {
            const int tb = r0 + rr * 8;
#pragma unroll
            for (int ni = 0; ni < 4; ni++) {
                const int oc = nWarp + ni * 8 + tig * 2;
                const int o = colBase + oc;
                const int h = o >> 5, f = o & 31;
                __half2 v = __floats2half2_rn(c[mi][ni][2 * rr + 0] + sbias[oc],
                                              c[mi][ni][2 * rr + 1] + sbias[oc + 1]);
                *(__half2*)&g_q[(((size_t)tb * H_ + h) * N_ + nJ) * F_ + f] = v;
            }
        }
    }
}

// ---------------------------------------------------------------------------
// Kernel 3: tensor-core attention (unchanged from R11, validated).
// ---------------------------------------------------------------------------
#define AROW 20   // words per smem row (conflict-free)

__global__ __launch_bounds__(128)
void attn_kernel(float* __restrict__ out)
{
    __shared__ uint32_t sm[4][3][32 * AROW];

    const int tb   = blockIdx.x;
    const int w    = threadIdx.x >> 5;
    const int lane = threadIdx.x & 31;
    const int gid  = lane >> 2, tig = lane & 3;
    const int h    = blockIdx.y * 4 + w;

    uint32_t* qs = sm[w][0];
    uint32_t* ks = sm[w][1];
    uint32_t* vs = sm[w][2];

    const size_t base = ((size_t)(tb * H_ + h)) * N_ * F_;
    const uint2* qg = (const uint2*)(g_q + base);
    const uint2* kg = (const uint2*)(g_k + base);
    const uint2* vg = (const uint2*)(g_v + base);

    for (int i = lane; i < 24 * 8; i += 32) {
        const int r = i >> 3, cc = i & 7;
        *(uint2*)&qs[r * AROW + cc * 2] = qg[i];
        *(uint2*)&ks[r * AROW + cc * 2] = kg[i];
    }
    __half* vsh = (__half*)vs;
    for (int i = lane; i < 24 * 8; i += 32) {
        const int m = i >> 3, cc = i & 7;
        uint2 u = vg[i];
        __half2 h01 = *(__half2*)&u.x, h23 = *(__half2*)&u.y;
        const int f0 = cc * 4;
        vsh[(f0 + 0) * (2 * AROW) + m] = __low2half(h01);
        vsh[(f0 + 1) * (2 * AROW) + m] = __high2half(h01);
        vsh[(f0 + 2) * (2 * AROW) + m] = __low2half(h23);
        vsh[(f0 + 3) * (2 * AROW) + m] = __high2half(h23);
    }
    *(uint4*)&vsh[lane * (2 * AROW) + 24] = make_uint4(0, 0, 0, 0);
    __syncwarp();

    float cs[2][3][4];
#pragma unroll
    for (int mi = 0; mi < 2; mi++)
#pragma unroll
        for (int ni = 0; ni < 3; ni++)
#pragma unroll
            for (int j = 0; j < 4; j++) cs[mi][ni][j] = 0.f;

#pragma unroll
    for (int kb = 0; kb < 2; kb++) {
        uint32_t a[2][4];
#pragma unroll
        for (int mi = 0; mi < 2; mi++) {
            const int r = mi * 16 + gid;
            a[mi][0] = qs[(r)     * AROW + kb * 8 + tig];
            a[mi][1] = qs[(r + 8) * AROW + kb * 8 + tig];
            a[mi][2] = qs[(r)     * AROW + kb * 8 + tig + 4];
            a[mi][3] = qs[(r + 8) * AROW + kb * 8 + tig + 4];
        }
#pragma unroll
        for (int ni = 0; ni < 3; ni++) {
            uint32_t b[2];
            b[0] = ks[(ni * 8 + gid) * AROW + kb * 8 + tig];
            b[1] = ks[(ni * 8 + gid) * AROW + kb * 8 + tig + 4];
#pragma unroll
            for (int mi = 0; mi < 2; mi++) mma_f16(cs[mi][ni], a[mi], b);
        }
    }

    const float scale = 0.17677669529663687f;  // 1/sqrt(32)
    float p[2][3][4];
#pragma unroll
    for (int mi = 0; mi < 2; mi++) {
        float m0 = -1e30f, m1 = -1e30f;
#pragma unroll
        for (int ni = 0; ni < 3; ni++) {
            m0 = fmaxf(m0, fmaxf(cs[mi][ni][0], cs[mi][ni][1]));
            m1 = fmaxf(m1, fmaxf(cs[mi][ni][2], cs[mi][ni][3]));
        }
        m0 = fmaxf(m0, __shfl_xor_sync(0xffffffffu, m0, 1));
        m0 = fmaxf(m0, __shfl_xor_sync(0xffffffffu, m0, 2));
        m1 = fmaxf(m1, __shfl_xor_sync(0xffffffffu, m1, 1));
        m1 = fmaxf(m1, __shfl_xor_sync(0xffffffffu, m1, 2));

        float s0 = 0.f, s1 = 0.f;
#pragma unroll
        for (int ni = 0; ni < 3; ni++) {
            p[mi][ni][0] = __expf((cs[mi][ni][0] - m0) * scale);
            p[mi][ni][1] = __expf((cs[mi][ni][1] - m0) * scale);
            p[mi][ni][2] = __expf((cs[mi][ni][2] - m1) * scale);
            p[mi][ni][3] = __expf((cs[mi][ni][3] - m1) * scale);
            s0 += p[mi][ni][0] + p[mi][ni][1];
            s1 += p[mi][ni][2] + p[mi][ni][3];
        }
        s0 += __shfl_xor_sync(0xffffffffu, s0, 1);
        s0 += __shfl_xor_sync(0xffffffffu, s0, 2);
        s1 += __shfl_xor_sync(0xffffffffu, s1, 1);
        s1 += __shfl_xor_sync(0xffffffffu, s1, 2);
        const float i0 = __frcp_rn(s0), i1 = __frcp_rn(s1);
#pragma unroll
        for (int ni = 0; ni < 3; ni++) {
            p[mi][ni][0] *= i0; p[mi][ni][1] *= i0;
            p[mi][ni][2] *= i1; p[mi][ni][3] *= i1;
        }
    }

    float co[2][4][4];
#pragma unroll
    for (int mi = 0; mi < 2; mi++)
#pragma unroll
        for (int nj = 0; nj < 4; nj++)
#pragma unroll
            for (int j = 0; j < 4; j++) co[mi][nj][j] = 0.f;

#pragma unroll
    for (int mi = 0; mi < 2; mi++) {
        uint32_t ap0[4], ap1[4];
        ap0[0] = packh2(p[mi][0][0], p[mi][0][1]);
        ap0[1] = packh2(p[mi][0][2], p[mi][0][3]);
        ap0[2] = packh2(p[mi][1][0], p[mi][1][1]);
        ap0[3] = packh2(p[mi][1][2], p[mi][1][3]);
        ap1[0] = packh2(p[mi][2][0], p[mi][2][1]);
        ap1[1] = packh2(p[mi][2][2], p[mi][2][3]);
        ap1[2] = 0u; ap1[3] = 0u;
#pragma unroll
        for (int nj = 0; nj < 4; nj++) {
            uint32_t b0[2], b1[2];
            b0[0] = vs[(nj * 8 + gid) * AROW + tig];
            b0[1] = vs[(nj * 8 + gid) * AROW + tig + 4];
            b1[0] = vs[(nj * 8 + gid) * AROW + 8 + tig];
            b1[1] = vs[(nj * 8 + gid) * AROW + 8 + tig + 4];
            mma_f16(co[mi][nj], ap0, b0);
            mma_f16(co[mi][nj], ap1, b1);
        }
    }

#pragma unroll
    for (int mi = 0; mi < 2; mi++) {
        const int r0 = mi * 16 + gid;
#pragma unroll
        for (int nj = 0; nj < 4; nj++) {
            const int fcol = nj * 8 + 2 * tig;
            float2 v0;
            v0.x = co[mi][nj][0]; v0.y = co[mi][nj][1];
            *(float2*)&out[(size_t)tb * OUTW_ + (r0 * H_ + h) * F_ + fcol] = v0;
            if (mi == 0) {
                float2 v1;
                v1.x = co[mi][nj][2]; v1.y = co[mi][nj][3];
                *(float2*)&out[(size_t)tb * OUTW_ + ((r0 + 8) * H_ + h) * F_ + fcol] = v1;
            }
        }
    }
}

// ---------------------------------------------------------------------------
extern "C" void kernel_launch(void* const* d_in, const int* in_sizes, int n_in,
                              void* d_out, int out_size)
{
    const float* x  = (const float*)d_in[0];
    const float* Wk = (const float*)d_in[1];
    const float* bk = (const float*)d_in[2];
    const float* Wv = (const float*)d_in[3];
    const float* bv = (const float*)d_in[4];
    const float* Wq = (const float*)d_in[5];
    const float* bq = (const float*)d_in[6];
    float* out = (float*)d_out;

    cudaFuncSetAttribute(kv_mma_kernel,
                         cudaFuncAttributeMaxDynamicSharedMemorySize, KV_SMEM);
    cudaFuncSetAttribute(q_mma_kernel,
                         cudaFuncAttributeMaxDynamicSharedMemorySize, Q_SMEM);

    void* xh; void* wkh; void* wvh; void* wqh;
    cudaGetSymbolAddress(&xh,  g_xh);
    cudaGetSymbolAddress(&wkh, g_wkh);
    cudaGetSymbolAddress(&wvh, g_wvh);
    cudaGetSymbolAddress(&wqh, g_wqh);

    // Pre-pass: fp32 -> fp16 once.
    conv_h_kernel<<<8192, 256>>>((const float4*)x,  (uint2*)xh,  TB_ * ND_ / 4);
    conv_h_kernel<<<64,   256>>>((const float4*)Wk, (uint2*)wkh, HF_ * D_ / 4);
    conv_h_kernel<<<64,   256>>>((const float4*)Wv, (uint2*)wvh, HF_ * D_ / 4);
    conv_h_kernel<<<1536, 256>>>((const float4*)Wq, (uint2*)wqh, H_ * N_ * F_ * D_ / 4);

    dim3 g1(2, M1_ / 128);
    kv_mma_kernel<<<g1, 256, KV_SMEM>>>(bk, bv);

    dim3 g2(2, N_, TB_ / 128);
    q_mma_kernel<<<g2, 256, Q_SMEM>>>(bq);

    dim3 g3(TB_, 2);
    attn_kernel<<<g3, 128>>>(out);
}